// round 7
// baseline (speedup 1.0000x reference)
#include <cuda_runtime.h>
#include <cstddef>
#include <cstdint>

#define Bsz   1024
#define DF    2048
#define DIM   128
#define CC    8192
#define PP    8
#define NNq   4
#define NC    (NNq * CC)            // 32768
#define PC    (PP * CC)             // 65536
#define SIMW  (Bsz + PP + NNq * (CC - 1))  // 33796
#define SPLITK 16

static constexpr size_t OFF_SIM  = 0;
static constexpr size_t OFF_LAB  = (size_t)Bsz * SIMW;
static constexpr size_t OFF_LQ   = OFF_LAB + (size_t)Bsz * SIMW;
static constexpr size_t OFF_LK   = OFF_LQ + (size_t)Bsz * CC;
static constexpr size_t OFF_NQ2  = OFF_LK + (size_t)Bsz * CC;
static constexpr size_t OFF_PQ2  = OFF_NQ2 + (size_t)DIM * NC;
static constexpr size_t OFF_NPTR = OFF_PQ2 + (size_t)DIM * PC;
static constexpr size_t OFF_PPTR = OFF_NPTR + CC;

// ---------------- device scratch ------------------------------------------
__device__ float g_Hq[(size_t)Bsz * DF];
__device__ float g_Hk[(size_t)Bsz * DF];
__device__ float g_HqR[(size_t)Bsz * DF];     // BN+relu, rounded, k-permuted
__device__ float g_HkR[(size_t)Bsz * DF];
__device__ float g_midqR[(size_t)Bsz * DF];   // rounded, k-permuted
__device__ float g_midkR[(size_t)Bsz * DF];
__device__ float g_scq[DF], g_shq[DF], g_sck[DF], g_shk[DF];
__device__ float g_featq[(size_t)Bsz * DIM];
__device__ float g_featk[(size_t)Bsz * DIM];
__device__ float g_featqR[(size_t)Bsz * DIM]; // rounded, k-permuted
__device__ float g_fpart[(size_t)2 * SPLITK * Bsz * DIM];
__device__ int   g_rank[Bsz];
__device__ int   g_cntb[Bsz];

// ---------------- helpers --------------------------------------------------
__device__ __forceinline__ unsigned f2tf(float x) {
    unsigned u;
    asm("cvt.rna.tf32.f32 %0, %1;" : "=r"(u) : "f"(x));
    return u;
}
__device__ __forceinline__ float rna(float x) { return __uint_as_float(f2tf(x)); }

// k-permutation within 8-groups: logical t stored at (t&3)*2 + (t>>2)
// => pair (t, t+4) contiguous as one float2 at float2-index t (in group)
__device__ __host__ __forceinline__ int prm8(int t) { return ((t & 3) << 1) + (t >> 2); }
__device__ __forceinline__ int prm(int idx) { return (idx & ~7) | prm8(idx & 7); }

__device__ __forceinline__ void mma_tf32(float c[4], const unsigned a[4],
                                         const unsigned b[2]) {
    asm volatile(
        "mma.sync.aligned.m16n8k8.row.col.f32.tf32.tf32.f32 "
        "{%0,%1,%2,%3}, {%4,%5,%6,%7}, {%8,%9}, {%0,%1,%2,%3};"
        : "+f"(c[0]), "+f"(c[1]), "+f"(c[2]), "+f"(c[3])
        : "r"(a[0]), "r"(a[1]), "r"(a[2]), "r"(a[3]), "r"(b[0]), "r"(b[1]));
}

__device__ __forceinline__ void cpa16(uint32_t saddr, const float* g) {
    asm volatile("cp.async.cg.shared.global [%0], [%1], 16;\n" :: "r"(saddr), "l"(g));
}
#define CP_COMMIT() asm volatile("cp.async.commit_group;\n" ::: "memory")
#define CP_WAIT2()  asm volatile("cp.async.wait_group 2;\n" ::: "memory")

// ---------------- TF32 mma.sync GEMM, 4-stage cp.async --------------------
// CTA 128x128, BK=16, 256 threads (8 warps, warp tile 64x32).
// A [M][K'] in gmem: RNA-rounded + k-permuted. Smem As[m][k'] stride 24:
//   fragment read = LDS.64 (pair k,k+4), banks 12g+tig mod 16: conflict-free.
// B  [K][N] natural fp32 (weights untouched!). Smem Bs[k][n] stride 136:
//   fragment banks 8*tig+g: conflict-free; cvt.rna at fragment read.
// MODE 0: +bias; z selects (A0,C0)/(A1,C1)
// MODE 2: split-K partial: z = qk*SPLITK + sk; C = C0 + z*Bsz*DIM
// MODE 3: B given as [N][K] (featk), transposed during staging
// MODE 4: neg scatter epilogue skipping labels[m]'s NNq columns
#define ASTR 24
#define BSTR 136
#define STAGEF (128 * ASTR + 16 * BSTR)   // 5248 floats per stage
template <int MODE>
__global__ void __launch_bounds__(256, 2) mm_k(
    const float* __restrict__ A0, const float* __restrict__ A1,
    const float* __restrict__ Bm, const float* __restrict__ bias,
    float* __restrict__ C0, float* __restrict__ C1,
    int K, int ldb, int ldc, const int* __restrict__ labels)
{
    extern __shared__ float smem[];

    const int tid   = threadIdx.x;
    const int lane  = tid & 31;
    const int warp  = tid >> 5;
    const int g     = lane >> 2;
    const int tig   = lane & 3;
    const int wm    = (warp & 1) * 64;
    const int wn    = (warp >> 1) * 32;
    const int mBase = blockIdx.y * 128;
    const int nBase = blockIdx.x * 128;

    int kBeg = 0, kEnd = K;
    const float* A;
    float* Cc;
    if (MODE == 2) {
        int qk = blockIdx.z >> 4;
        int sk = blockIdx.z & 15;
        kBeg = sk * (K / SPLITK);
        kEnd = kBeg + K / SPLITK;
        A  = qk ? A1 : A0;
        Cc = C0 + (size_t)blockIdx.z * ((size_t)Bsz * DIM);
    } else {
        A  = blockIdx.z ? A1 : A0;
        Cc = blockIdx.z ? C1 : C0;
    }

    const int nIter = (kEnd - kBeg) / 16;

    // staging: A 128x16 floats (512 chunks of 16B, 2/thread);
    //          B 16x128 floats (512 chunks, 2/thread) or transposed STS (MODE 3)
    const int ar  = tid >> 1;            // A row 0..127
    const int acb = (tid & 1) * 2;       // A chunk base {0,2}
    const int brk = tid >> 4;            // B row 0..15
    const int bcb = (tid & 15) * 2;      // B chunk base 0..30
    auto stage_load = [&](int s, int k0) {
        float* base = smem + s * STAGEF;
        uint32_t sA = (uint32_t)__cvta_generic_to_shared(base);
        uint32_t sB = sA + 128 * ASTR * 4;
        const float* srcA = A + (size_t)(mBase + ar) * K + k0;
        #pragma unroll
        for (int i = 0; i < 2; i++) {
            int c = acb + i;
            cpa16(sA + (uint32_t)(ar * ASTR * 4 + c * 16), srcA + c * 4);
        }
        if (MODE == 3) {
            // B given [N][K]: transpose-stage via regular ld/st
            float* Bs = base + 128 * ASTR;
            int n  = tid >> 1;
            int kq = (tid & 1) * 8;
            const float* src = Bm + (size_t)(nBase + n) * ldb + k0 + kq;
            float4 v0 = *(const float4*)(src);
            float4 v1 = *(const float4*)(src + 4);
            Bs[(kq + 0) * BSTR + n] = v0.x;
            Bs[(kq + 1) * BSTR + n] = v0.y;
            Bs[(kq + 2) * BSTR + n] = v0.z;
            Bs[(kq + 3) * BSTR + n] = v0.w;
            Bs[(kq + 4) * BSTR + n] = v1.x;
            Bs[(kq + 5) * BSTR + n] = v1.y;
            Bs[(kq + 6) * BSTR + n] = v1.z;
            Bs[(kq + 7) * BSTR + n] = v1.w;
        } else {
            const float* srcB = Bm + (size_t)(k0 + brk) * ldb + nBase;
            #pragma unroll
            for (int i = 0; i < 2; i++) {
                int c = bcb + i;
                cpa16(sB + (uint32_t)(brk * BSTR * 4 + c * 16), srcB + c * 4);
            }
        }
    };

    float acc[4][4][4] = {};

    #pragma unroll
    for (int p = 0; p < 3; p++) {
        if (p < nIter) stage_load(p, kBeg + p * 16);
        CP_COMMIT();
    }

    for (int it = 0; it < nIter; ++it) {
        CP_WAIT2();
        __syncthreads();
        if (it + 3 < nIter) stage_load((it + 3) & 3, kBeg + (it + 3) * 16);
        CP_COMMIT();

        const float* sbase = smem + (it & 3) * STAGEF;
        const float2* A2 = (const float2*)sbase;
        const float*  Bs = sbase + 128 * ASTR;
        #pragma unroll
        for (int kk = 0; kk < 16; kk += 8) {
            unsigned af[4][4], bf[4][2];
            const int fo = (kk >> 1) + tig;   // float2 offset within row
            #pragma unroll
            for (int mt = 0; mt < 4; mt++) {
                int r0 = wm + mt * 16 + g;
                float2 f0 = A2[r0 * 12 + fo];
                float2 f1 = A2[(r0 + 8) * 12 + fo];
                af[mt][0] = __float_as_uint(f0.x);
                af[mt][2] = __float_as_uint(f0.y);
                af[mt][1] = __float_as_uint(f1.x);
                af[mt][3] = __float_as_uint(f1.y);
            }
            #pragma unroll
            for (int nt = 0; nt < 4; nt++) {
                int nc = wn + nt * 8 + g;
                bf[nt][0] = f2tf(Bs[(kk + tig) * BSTR + nc]);
                bf[nt][1] = f2tf(Bs[(kk + tig + 4) * BSTR + nc]);
            }
            #pragma unroll
            for (int mt = 0; mt < 4; mt++)
                #pragma unroll
                for (int nt = 0; nt < 4; nt++)
                    mma_tf32(acc[mt][nt], af[mt], bf[nt]);
        }
    }
    __syncthreads();

    // ---- epilogue ----
    #pragma unroll
    for (int mt = 0; mt < 4; mt++) {
        int r0 = mBase + wm + mt * 16 + g;
        int r1 = r0 + 8;
        int la0 = 0, la1 = 0;
        if (MODE == 4) { la0 = labels[r0] * NNq; la1 = labels[r1] * NNq; }
        #pragma unroll
        for (int nt = 0; nt < 4; nt++) {
            int c = nBase + wn + nt * 8 + 2 * tig;
            const float* a4 = acc[mt][nt];
            if (MODE == 4) {
                int n0 = c, n1 = c + 1;
                if (n0 < la0)             Cc[(size_t)r0 * ldc + n0]       = a4[0];
                else if (n0 >= la0 + NNq) Cc[(size_t)r0 * ldc + n0 - NNq] = a4[0];
                if (n1 < la0)             Cc[(size_t)r0 * ldc + n1]       = a4[1];
                else if (n1 >= la0 + NNq) Cc[(size_t)r0 * ldc + n1 - NNq] = a4[1];
                if (n0 < la1)             Cc[(size_t)r1 * ldc + n0]       = a4[2];
                else if (n0 >= la1 + NNq) Cc[(size_t)r1 * ldc + n0 - NNq] = a4[2];
                if (n1 < la1)             Cc[(size_t)r1 * ldc + n1]       = a4[3];
                else if (n1 >= la1 + NNq) Cc[(size_t)r1 * ldc + n1 - NNq] = a4[3];
            } else {
                float bx = 0.f, by = 0.f;
                if (MODE == 0) { bx = bias[c]; by = bias[c + 1]; }
                float2 v0 = { a4[0] + bx, a4[1] + by };
                float2 v1 = { a4[2] + bx, a4[3] + by };
                *(float2*)(Cc + (size_t)r0 * ldc + c) = v0;
                *(float2*)(Cc + (size_t)r1 * ldc + c) = v1;
            }
        }
    }
}

// ---------------- prep: round + k-permute (8 floats / thread) --------------
__global__ void round_perm_k(const float* __restrict__ in0, const float* __restrict__ in1,
                             float* __restrict__ o0, float* __restrict__ o1, int n8)
{
    const float* in = blockIdx.z ? in1 : in0;
    float* o = blockIdx.z ? o1 : o0;
    int i = blockIdx.x * blockDim.x + threadIdx.x;
    if (i >= n8) return;
    float4 a = ((const float4*)in)[i * 2];
    float4 b = ((const float4*)in)[i * 2 + 1];
    float4 p0 = { rna(a.x), rna(b.x), rna(a.y), rna(b.y) };
    float4 p1 = { rna(a.z), rna(b.z), rna(a.w), rna(b.w) };
    ((float4*)o)[i * 2]     = p0;
    ((float4*)o)[i * 2 + 1] = p1;
}

// ---------------- BN stats -------------------------------------------------
__global__ void bn_stats_k(const float* __restrict__ Hq, const float* __restrict__ Hk,
                           const float* __restrict__ gamma, const float* __restrict__ beta,
                           float* __restrict__ scq, float* __restrict__ shq,
                           float* __restrict__ sck, float* __restrict__ shk)
{
    const float* H = blockIdx.z ? Hk : Hq;
    float* scale = blockIdx.z ? sck : scq;
    float* shift = blockIdx.z ? shk : shq;
    int f = blockIdx.x * 32 + threadIdx.x;
    float s = 0.f, ss = 0.f;
    for (int rr = threadIdx.y; rr < Bsz; rr += 32) {
        float v = H[(size_t)rr * DF + f];
        s += v; ss += v * v;
    }
    __shared__ float sh_s[32][33], sh_ss[32][33];
    sh_s[threadIdx.y][threadIdx.x]  = s;
    sh_ss[threadIdx.y][threadIdx.x] = ss;
    __syncthreads();
    if (threadIdx.y == 0) {
        #pragma unroll
        for (int y = 1; y < 32; y++) {
            s += sh_s[y][threadIdx.x]; ss += sh_ss[y][threadIdx.x];
        }
        float mu  = s * (1.f / Bsz);
        float var = ss * (1.f / Bsz) - mu * mu;
        float rst = rsqrtf(var + 1e-5f);
        float scv = rst * gamma[f];
        scale[f] = scv;
        shift[f] = beta[f] - mu * scv;
    }
}

// ---------------- BN apply + relu + round + k-permute ----------------------
__global__ void bnrelu_perm_k(const float* __restrict__ Hq, const float* __restrict__ Hk,
                              float* __restrict__ Rq, float* __restrict__ Rk)
{
    const float* H = blockIdx.z ? Hk : Hq;
    float* R = blockIdx.z ? Rk : Rq;
    const float* sc = blockIdx.z ? g_sck : g_scq;
    const float* sh = blockIdx.z ? g_shk : g_shq;
    int i = blockIdx.x * blockDim.x + threadIdx.x;   // 8-float group index
    int f = (i * 8) & (DF - 1);
    float4 a = ((const float4*)H)[i * 2];
    float4 b = ((const float4*)H)[i * 2 + 1];
    float4 sa = *(const float4*)(sc + f);
    float4 sb = *(const float4*)(sc + f + 4);
    float4 ha = *(const float4*)(sh + f);
    float4 hb = *(const float4*)(sh + f + 4);
    a.x = rna(fmaxf(fmaf(a.x, sa.x, ha.x), 0.f));
    a.y = rna(fmaxf(fmaf(a.y, sa.y, ha.y), 0.f));
    a.z = rna(fmaxf(fmaf(a.z, sa.z, ha.z), 0.f));
    a.w = rna(fmaxf(fmaf(a.w, sa.w, ha.w), 0.f));
    b.x = rna(fmaxf(fmaf(b.x, sb.x, hb.x), 0.f));
    b.y = rna(fmaxf(fmaf(b.y, sb.y, hb.y), 0.f));
    b.z = rna(fmaxf(fmaf(b.z, sb.z, hb.z), 0.f));
    b.w = rna(fmaxf(fmaf(b.w, sb.w, hb.w), 0.f));
    float4 p0 = { a.x, b.x, a.y, b.y };
    float4 p1 = { a.z, b.z, a.w, b.w };
    ((float4*)R)[i * 2]     = p0;
    ((float4*)R)[i * 2 + 1] = p1;
}

// ---------------- split-K reduce + bias + l2norm ---------------------------
__global__ void reduce_l2_k(const float* __restrict__ b2)
{
    int qk = blockIdx.y, b = blockIdx.x, d = threadIdx.x;  // d: 0..127
    const float* part = g_fpart + (size_t)qk * SPLITK * Bsz * DIM;
    float v = b2[d];
    #pragma unroll
    for (int s = 0; s < SPLITK; s++)
        v += part[(size_t)s * Bsz * DIM + (size_t)b * DIM + d];
    float ss = v * v;
    #pragma unroll
    for (int o = 16; o; o >>= 1) ss += __shfl_xor_sync(0xffffffffu, ss, o);
    __shared__ float ws[4];
    if ((d & 31) == 0) ws[d >> 5] = ss;
    __syncthreads();
    ss = ws[0] + ws[1] + ws[2] + ws[3];
    float inv = 1.f / fmaxf(sqrtf(ss), 1e-12f);
    float vn = v * inv;
    if (qk) {
        g_featk[(size_t)b * DIM + d] = vn;          // plain (MODE3 B side + queue)
    } else {
        g_featq[(size_t)b * DIM + d] = vn;          // plain (pos_k)
        g_featqR[(size_t)b * DIM + prm(d)] = rna(vn); // A side (sim, neg)
    }
}

// ---------------- pos_list --------------------------------------------------
__global__ void pos_k(const int* __restrict__ lq, const float* __restrict__ posq,
                      float* __restrict__ out)
{
    int b = blockIdx.x, tid = threadIdx.x;
    __shared__ float fr[DIM];
    if (tid < DIM) fr[tid] = g_featq[(size_t)b * DIM + tid];
    __syncthreads();
    int w = tid >> 5, lane = tid & 31;
    int col = lq[b] * PP + w;
    float s = 0.f;
    for (int d = lane; d < DIM; d += 32)
        s += fr[d] * posq[(size_t)d * PC + col];
    #pragma unroll
    for (int o = 16; o; o >>= 1) s += __shfl_down_sync(0xffffffffu, s, o);
    if (lane == 0) out[OFF_SIM + (size_t)b * SIMW + Bsz + w] = s;
}

// ---------------- labels_con fill ------------------------------------------
__global__ void labels_fill_k(const int* __restrict__ lq, const int* __restrict__ lk,
                              float* __restrict__ out)
{
    size_t i4 = (size_t)blockIdx.x * blockDim.x + threadIdx.x;
    const size_t total4 = (size_t)Bsz * (SIMW / 4);
    if (i4 >= total4) return;
    int row = (int)(i4 / (SIMW / 4));
    int c0  = (int)(i4 % (SIMW / 4)) * 4;
    float4 v;
    if (c0 + 4 <= Bsz) {
        int l = lq[row];
        v.x = (lk[c0 + 0] == l) ? 1.f : 0.f;
        v.y = (lk[c0 + 1] == l) ? 1.f : 0.f;
        v.z = (lk[c0 + 2] == l) ? 1.f : 0.f;
        v.w = (lk[c0 + 3] == l) ? 1.f : 0.f;
    } else if (c0 >= Bsz && c0 + 4 <= Bsz + PP) {
        v.x = v.y = v.z = v.w = 1.f;
    } else {
        v.x = v.y = v.z = v.w = 0.f;
    }
    *(float4*)(out + OFF_LAB + (size_t)row * SIMW + c0) = v;
}

// ---------------- occurrence rank + count (warp-per-row) -------------------
__global__ void rank_k(const int* __restrict__ lk)
{
    __shared__ int sl[Bsz];
    int t = threadIdx.y * 32 + threadIdx.x;
    for (int i = t; i < Bsz; i += 1024) sl[i] = lk[i];
    __syncthreads();
    int b = blockIdx.x * 32 + threadIdx.y;
    int lab = sl[b];
    int r = 0, c = 0;
    for (int j = threadIdx.x; j < Bsz; j += 32) {
        int e = (sl[j] == lab);
        c += e;
        r += e & (j < b);
    }
    #pragma unroll
    for (int o = 16; o; o >>= 1) {
        c += __shfl_down_sync(0xffffffffu, c, o);
        r += __shfl_down_sync(0xffffffffu, r, o);
    }
    if (threadIdx.x == 0) { g_rank[b] = r; g_cntb[b] = c; }
}

// ---------------- ptr outputs (warp-per-class) -----------------------------
__global__ void ptr_k(const int* __restrict__ lk, const int* __restrict__ nptr,
                      const int* __restrict__ pptr, float* __restrict__ out)
{
    __shared__ int sl[Bsz];
    for (int i = threadIdx.x; i < Bsz; i += 256) sl[i] = lk[i];
    __syncthreads();
    int w = threadIdx.x >> 5, lane = threadIdx.x & 31;
    int c = blockIdx.x * 8 + w;
    int cnt = 0;
    for (int j = lane; j < Bsz; j += 32) cnt += (sl[j] == c);
    #pragma unroll
    for (int o = 16; o; o >>= 1) cnt += __shfl_down_sync(0xffffffffu, cnt, o);
    if (lane == 0) {
        out[OFF_NPTR + c] = (float)((nptr[c] + cnt) % NNq);
        out[OFF_PPTR + c] = (float)((pptr[c] + cnt) % PP);
    }
}

// ---------------- queue overwrite ------------------------------------------
__global__ void queue_update_k(const int* __restrict__ lk, const int* __restrict__ nptr,
                               const int* __restrict__ pptr, float* __restrict__ out)
{
    int b = blockIdx.x;
    int d = threadIdx.x;   // 128
    int lab = lk[b];
    int r = g_rank[b];
    int c = g_cntb[b];
    float v = g_featk[(size_t)b * DIM + d];
    if (r >= c - NNq) {
        int slot = (nptr[lab] + r) % NNq;
        out[OFF_NQ2 + (size_t)d * NC + lab * NNq + slot] = v;
    }
    if (r >= c - PP) {
        int slot = (pptr[lab] + r) % PP;
        out[OFF_PQ2 + (size_t)d * PC + lab * PP + slot] = v;
    }
}

// ---------------- host launcher --------------------------------------------
static float* symf(const void* sym) {
    void* p = nullptr;
    cudaGetSymbolAddress(&p, sym);
    return (float*)p;
}

extern "C" void kernel_launch(void* const* d_in, const int* in_sizes, int n_in,
                              void* d_out, int out_size)
{
    (void)in_sizes; (void)n_in; (void)out_size;
    const float* midq  = (const float*)d_in[0];
    const float* midk  = (const float*)d_in[1];
    const int*   lq    = (const int*)d_in[2];
    const int*   lk    = (const int*)d_in[3];
    const float* W1    = (const float*)d_in[4];
    const float* b1    = (const float*)d_in[5];
    const float* gamma = (const float*)d_in[6];
    const float* beta  = (const float*)d_in[7];
    const float* W2    = (const float*)d_in[8];
    const float* b2    = (const float*)d_in[9];
    const float* Wlin  = (const float*)d_in[10];
    const float* blin  = (const float*)d_in[11];
    const float* negq  = (const float*)d_in[12];
    const float* posq  = (const float*)d_in[13];
    const int*   nptr  = (const int*)d_in[14];
    const int*   pptr  = (const int*)d_in[15];
    float* out = (float*)d_out;

    float* Hq    = symf(g_Hq);
    float* Hk    = symf(g_Hk);
    float* HqR   = symf(g_HqR);
    float* HkR   = symf(g_HkR);
    float* midqR = symf(g_midqR);
    float* midkR = symf(g_midkR);
    float* fqR   = symf(g_featqR);
    float* fk    = symf(g_featk);
    float* fpart = symf(g_fpart);

    const int SMSZ = 4 * STAGEF * 4;   // 83968 bytes
    cudaFuncSetAttribute(mm_k<0>, cudaFuncAttributeMaxDynamicSharedMemorySize, SMSZ);
    cudaFuncSetAttribute(mm_k<2>, cudaFuncAttributeMaxDynamicSharedMemorySize, SMSZ);
    cudaFuncSetAttribute(mm_k<3>, cudaFuncAttributeMaxDynamicSharedMemorySize, SMSZ);
    cudaFuncSetAttribute(mm_k<4>, cudaFuncAttributeMaxDynamicSharedMemorySize, SMSZ);

    // queues copied to output (queue_update overwrites survivors)
    cudaMemcpyAsync(out + OFF_NQ2, negq, sizeof(float) * (size_t)DIM * NC,
                    cudaMemcpyDeviceToDevice);
    cudaMemcpyAsync(out + OFF_PQ2, posq, sizeof(float) * (size_t)DIM * PC,
                    cudaMemcpyDeviceToDevice);

    // ---- prep: round+permute the A-side activations (weights untouched) ----
    round_perm_k<<<dim3(Bsz * DF / 8 / 256, 1, 2), 256>>>(
        midq, midk, midqR, midkR, Bsz * DF / 8);

    // ---- logits: mid @ Wlin + blin ----
    mm_k<0><<<dim3(CC / 128, Bsz / 128, 2), 256, SMSZ>>>(
        midqR, midkR, Wlin, blin, out + OFF_LQ, out + OFF_LK, DF, CC, CC, nullptr);

    // ---- H = mid @ W1 + b1 ----
    mm_k<0><<<dim3(DF / 128, Bsz / 128, 2), 256, SMSZ>>>(
        midqR, midkR, W1, b1, Hq, Hk, DF, DF, DF, nullptr);

    // ---- BN stats + apply(relu)+round+permute ----
    bn_stats_k<<<dim3(DF / 32, 1, 2), dim3(32, 32)>>>(
        Hq, Hk, gamma, beta, symf(g_scq), symf(g_shq), symf(g_sck), symf(g_shk));
    bnrelu_perm_k<<<dim3(Bsz * DF / 8 / 256, 1, 2), 256>>>(Hq, Hk, HqR, HkR);

    // ---- feat partials = relu(BN(H)) @ W2 (split-K 16, q/k via z) ----
    mm_k<2><<<dim3(1, Bsz / 128, 2 * SPLITK), 256, SMSZ>>>(
        HqR, HkR, W2, nullptr, fpart, nullptr, DF, DIM, DIM, nullptr);

    // ---- reduce + bias + l2norm ----
    reduce_l2_k<<<dim3(Bsz, 2), DIM>>>(b2);

    // ---- sim_batch = feat_q @ feat_k^T (B = featk [N][K], transposed stage) ----
    mm_k<3><<<dim3(Bsz / 128, Bsz / 128, 1), 256, SMSZ>>>(
        fqR, nullptr, fk, nullptr, out + OFF_SIM, nullptr, DIM, DIM, SIMW, nullptr);

    // ---- pos_list ----
    pos_k<<<Bsz, 256>>>(lq, posq, out);

    // ---- neg gathered (B = negq [DIM][NC] natural) ----
    mm_k<4><<<dim3(NC / 128, Bsz / 128, 1), 256, SMSZ>>>(
        fqR, nullptr, negq, nullptr, out + OFF_SIM + Bsz + PP, nullptr,
        DIM, NC, SIMW, lq);

    // ---- labels_con ----
    {
        size_t total4 = (size_t)Bsz * (SIMW / 4);
        int blocks = (int)((total4 + 255) / 256);
        labels_fill_k<<<blocks, 256>>>(lq, lk, out);
    }

    // ---- queue update ----
    rank_k<<<32, dim3(32, 32)>>>(lk);
    ptr_k<<<CC / 8, 256>>>(lk, nptr, pptr, out);
    queue_update_k<<<Bsz, DIM>>>(lk, nptr, pptr, out);
}

// round 8
// speedup vs baseline: 1.1214x; 1.1214x over previous
#include <cuda_runtime.h>
#include <cstddef>
#include <cstdint>

#define Bsz   1024
#define DF    2048
#define DIM   128
#define CC    8192
#define PP    8
#define NNq   4
#define NC    (NNq * CC)            // 32768
#define PC    (PP * CC)             // 65536
#define SIMW  (Bsz + PP + NNq * (CC - 1))  // 33796
#define SPLITK 16

static constexpr size_t OFF_SIM  = 0;
static constexpr size_t OFF_LAB  = (size_t)Bsz * SIMW;
static constexpr size_t OFF_LQ   = OFF_LAB + (size_t)Bsz * SIMW;
static constexpr size_t OFF_LK   = OFF_LQ + (size_t)Bsz * CC;
static constexpr size_t OFF_NQ2  = OFF_LK + (size_t)Bsz * CC;
static constexpr size_t OFF_PQ2  = OFF_NQ2 + (size_t)DIM * NC;
static constexpr size_t OFF_NPTR = OFF_PQ2 + (size_t)DIM * PC;
static constexpr size_t OFF_PPTR = OFF_NPTR + CC;

// ---------------- device scratch (no allocations allowed) ----------------
__device__ float g_Hq[(size_t)Bsz * DF];
__device__ float g_Hk[(size_t)Bsz * DF];
__device__ float g_scq[DF], g_shq[DF], g_sck[DF], g_shk[DF];
__device__ float g_featq[(size_t)Bsz * DIM];
__device__ float g_featk[(size_t)Bsz * DIM];
__device__ float g_fpart[(size_t)2 * SPLITK * Bsz * DIM];
__device__ int   g_rank[Bsz];
__device__ int   g_cntb[Bsz];

// ---------------- helpers -------------------------------------------------
__device__ __forceinline__ unsigned f2tf(float x) {
    unsigned u;
    asm("cvt.rna.tf32.f32 %0, %1;" : "=r"(u) : "f"(x));
    return u;
}

__device__ __forceinline__ void mma_tf32(float c[4], const unsigned a[4],
                                         const unsigned b[2]) {
    asm volatile(
        "mma.sync.aligned.m16n8k8.row.col.f32.tf32.tf32.f32 "
        "{%0,%1,%2,%3}, {%4,%5,%6,%7}, {%8,%9}, {%0,%1,%2,%3};"
        : "+f"(c[0]), "+f"(c[1]), "+f"(c[2]), "+f"(c[3])
        : "r"(a[0]), "r"(a[1]), "r"(a[2]), "r"(a[3]), "r"(b[0]), "r"(b[1]));
}

__device__ __forceinline__ void cpa16(uint32_t saddr, const float* g) {
    asm volatile("cp.async.cg.shared.global [%0], [%1], 16;\n"
                 :: "r"(saddr), "l"(g));
}
#define CP_COMMIT() asm volatile("cp.async.commit_group;\n" ::: "memory")
#define CP_WAIT1()  asm volatile("cp.async.wait_group 1;\n" ::: "memory")
#define CP_WAIT0()  asm volatile("cp.async.wait_group 0;\n" ::: "memory")

// ---------------- TF32 tensor-core GEMM, cp.async double-buffered ---------
// 128x128 block tile, BK=16, 256 threads (8 warps, warp tile 64x32).
// As layout [m][k] stride 20 (frag banks 20g+tig: conflict-free)
// Bs layout [k][n] stride 136 (frag banks 8t+g: conflict-free)
// MODE 0: C = A@B + bias.              z selects (A0,C0) vs (A1,C1)
// MODE 2: A' = relu(A*sc+sh) at frag read; z = qk*SPLITK + sk partials
// MODE 3: B transposed (B[k][n] = Bm[n*ldb+k]); ALSO writes labels_batch
//         (lkk[n]==lqq[m]) into Lab mirror.
// MODE 4: neg epilogue: scatter skipping lqq[m]'s NNq columns; ALSO writes
//         0.0f into Lab mirror at each written position.
#define ASTR 20
#define BSTR 136
template <int MODE>
__global__ __launch_bounds__(256, 2) void tgemm_k(
    const float* __restrict__ A0, const float* __restrict__ A1,
    const float* __restrict__ Bm, const float* __restrict__ bias,
    float* __restrict__ C0, float* __restrict__ C1,
    int K, int lda, int ldb, int ldc,
    const float* __restrict__ sc0, const float* __restrict__ sh0,
    const float* __restrict__ sc1, const float* __restrict__ sh1,
    const int* __restrict__ lqq, const int* __restrict__ lkk,
    float* __restrict__ Lab)
{
    __shared__ float As[2][128 * ASTR];
    __shared__ float Bs[2][16 * BSTR];
    __shared__ float scs[2][16], shs[2][16];

    const int tid   = threadIdx.x;
    const int mBase = blockIdx.y * 128;
    const int nBase = blockIdx.x * 128;
    const int lane  = tid & 31;
    const int warp  = tid >> 5;
    const int g     = lane >> 2;
    const int tig   = lane & 3;
    const int wm    = (warp & 1) * 64;
    const int wn    = (warp >> 1) * 32;

    int kBeg = 0, kEnd = K;
    const float* A;
    float* Cc;
    const float* sc = nullptr;
    const float* sh = nullptr;
    if (MODE == 2) {
        int qk  = blockIdx.z >> 4;
        int skc = blockIdx.z & 15;
        kBeg = skc * (K / SPLITK);
        kEnd = kBeg + K / SPLITK;
        A  = qk ? A1 : A0;
        sc = qk ? sc1 : sc0;
        sh = qk ? sh1 : sh0;
        Cc = C0 + (size_t)blockIdx.z * ((size_t)Bsz * DIM);
    } else {
        A  = blockIdx.z ? A1 : A0;
        Cc = blockIdx.z ? C1 : C0;
    }

    uint32_t asA = (uint32_t)__cvta_generic_to_shared(&As[0][0]);
    uint32_t asB = (uint32_t)__cvta_generic_to_shared(&Bs[0][0]);

    // staging coordinates
    const int amc = tid >> 2;            // A chunk row (per 256-chunk pass)
    const int akc = (tid & 3) << 2;      // A chunk k-offset
    const int bkc = tid >> 5;            // B chunk row
    const int bnc = (tid & 31) << 2;     // B chunk n-offset

    auto load_tiles = [&](int s, int kpos) {
        // A: 128x16 floats = 512 chunks; 2 per thread
        #pragma unroll
        for (int i = 0; i < 2; i++) {
            int m = amc + i * 64;
            cpa16(asA + (uint32_t)((s * 128 * ASTR + m * ASTR + akc) * 4),
                  A + (size_t)(mBase + m) * lda + kpos + akc);
        }
        if (MODE != 3) {
            // B: 16x128 floats = 512 chunks; 2 per thread
            #pragma unroll
            for (int i = 0; i < 2; i++) {
                int k = bkc + i * 8;
                cpa16(asB + (uint32_t)((s * 16 * BSTR + k * BSTR + bnc) * 4),
                      Bm + (size_t)(kpos + k) * ldb + nBase + bnc);
            }
        } else {
            // transposed staging via regular ld/st (tiny GEMM)
            int n  = tid >> 1;
            int kq = (tid & 1) * 8;
            float4 v0 = *(const float4*)(Bm + (size_t)(nBase + n) * ldb + kpos + kq);
            float4 v1 = *(const float4*)(Bm + (size_t)(nBase + n) * ldb + kpos + kq + 4);
            Bs[s][(kq + 0) * BSTR + n] = v0.x;
            Bs[s][(kq + 1) * BSTR + n] = v0.y;
            Bs[s][(kq + 2) * BSTR + n] = v0.z;
            Bs[s][(kq + 3) * BSTR + n] = v0.w;
            Bs[s][(kq + 4) * BSTR + n] = v1.x;
            Bs[s][(kq + 5) * BSTR + n] = v1.y;
            Bs[s][(kq + 6) * BSTR + n] = v1.z;
            Bs[s][(kq + 7) * BSTR + n] = v1.w;
        }
        if (MODE == 2 && tid < 8) {
            const float* src = (tid < 4) ? sc : sh;
            float* dst = (tid < 4) ? scs[s] : shs[s];
            int t = tid & 3;
            *(float4*)(dst + t * 4) = *(const float4*)(src + kpos + t * 4);
        }
    };

    float acc[4][4][4] = {};

    const int nIter = (kEnd - kBeg) / 16;
    load_tiles(0, kBeg);
    CP_COMMIT();

    for (int it = 0; it < nIter; ++it) {
        int s = it & 1;
        if (it + 1 < nIter) {
            load_tiles(s ^ 1, kBeg + (it + 1) * 16);
            CP_COMMIT();
            CP_WAIT1();
        } else {
            CP_WAIT0();
        }
        __syncthreads();

        const float* as = As[s];
        const float* bs = Bs[s];
        #pragma unroll
        for (int kk = 0; kk < 16; kk += 8) {
            float c0 = 0.f, c1 = 0.f, d0 = 0.f, d1 = 0.f;
            if (MODE == 2) {
                c0 = scs[s][kk + tig];     d0 = shs[s][kk + tig];
                c1 = scs[s][kk + tig + 4]; d1 = shs[s][kk + tig + 4];
            }
            unsigned af[4][4], bf[4][2];
            #pragma unroll
            for (int mt = 0; mt < 4; mt++) {
                int mr = wm + mt * 16 + g;
                float a0 = as[mr * ASTR + kk + tig];
                float a1 = as[(mr + 8) * ASTR + kk + tig];
                float a2 = as[mr * ASTR + kk + tig + 4];
                float a3 = as[(mr + 8) * ASTR + kk + tig + 4];
                if (MODE == 2) {
                    a0 = fmaxf(fmaf(a0, c0, d0), 0.f);
                    a1 = fmaxf(fmaf(a1, c0, d0), 0.f);
                    a2 = fmaxf(fmaf(a2, c1, d1), 0.f);
                    a3 = fmaxf(fmaf(a3, c1, d1), 0.f);
                }
                af[mt][0] = f2tf(a0); af[mt][1] = f2tf(a1);
                af[mt][2] = f2tf(a2); af[mt][3] = f2tf(a3);
            }
            #pragma unroll
            for (int nt = 0; nt < 4; nt++) {
                int nc = wn + nt * 8 + g;
                bf[nt][0] = f2tf(bs[(kk + tig) * BSTR + nc]);
                bf[nt][1] = f2tf(bs[(kk + tig + 4) * BSTR + nc]);
            }
            #pragma unroll
            for (int mt = 0; mt < 4; mt++)
                #pragma unroll
                for (int nt = 0; nt < 4; nt++)
                    mma_tf32(acc[mt][nt], af[mt], bf[nt]);
        }
        __syncthreads();
    }

    // ---- epilogue ----
    #pragma unroll
    for (int mt = 0; mt < 4; mt++) {
        int r0 = mBase + wm + mt * 16 + g;
        int r1 = r0 + 8;
        int la0 = 0, la1 = 0;
        int lb0 = 0, lb1 = 0;
        if (MODE == 4) { la0 = lqq[r0] * NNq; la1 = lqq[r1] * NNq; }
        if (MODE == 3) { lb0 = lqq[r0]; lb1 = lqq[r1]; }
        #pragma unroll
        for (int nt = 0; nt < 4; nt++) {
            int c = nBase + wn + nt * 8 + 2 * tig;
            const float* a4 = acc[mt][nt];
            if (MODE == 4) {
                int n0 = c, n1 = c + 1;
                if (n0 < la0) {
                    Cc [(size_t)r0 * ldc + n0] = a4[0];
                    Lab[(size_t)r0 * ldc + n0] = 0.f;
                } else if (n0 >= la0 + NNq) {
                    Cc [(size_t)r0 * ldc + n0 - NNq] = a4[0];
                    Lab[(size_t)r0 * ldc + n0 - NNq] = 0.f;
                }
                if (n1 < la0) {
                    Cc [(size_t)r0 * ldc + n1] = a4[1];
                    Lab[(size_t)r0 * ldc + n1] = 0.f;
                } else if (n1 >= la0 + NNq) {
                    Cc [(size_t)r0 * ldc + n1 - NNq] = a4[1];
                    Lab[(size_t)r0 * ldc + n1 - NNq] = 0.f;
                }
                if (n0 < la1) {
                    Cc [(size_t)r1 * ldc + n0] = a4[2];
                    Lab[(size_t)r1 * ldc + n0] = 0.f;
                } else if (n0 >= la1 + NNq) {
                    Cc [(size_t)r1 * ldc + n0 - NNq] = a4[2];
                    Lab[(size_t)r1 * ldc + n0 - NNq] = 0.f;
                }
                if (n1 < la1) {
                    Cc [(size_t)r1 * ldc + n1] = a4[3];
                    Lab[(size_t)r1 * ldc + n1] = 0.f;
                } else if (n1 >= la1 + NNq) {
                    Cc [(size_t)r1 * ldc + n1 - NNq] = a4[3];
                    Lab[(size_t)r1 * ldc + n1 - NNq] = 0.f;
                }
            } else {
                float bx = 0.f, by = 0.f;
                if (MODE == 0) { bx = bias[c]; by = bias[c + 1]; }
                float2 v0 = { a4[0] + bx, a4[1] + by };
                float2 v1 = { a4[2] + bx, a4[3] + by };
                *(float2*)(Cc + (size_t)r0 * ldc + c) = v0;
                *(float2*)(Cc + (size_t)r1 * ldc + c) = v1;
                if (MODE == 3) {
                    int k0c = lkk[c], k1c = lkk[c + 1];
                    float2 l0 = { (k0c == lb0) ? 1.f : 0.f,
                                  (k1c == lb0) ? 1.f : 0.f };
                    float2 l1 = { (k0c == lb1) ? 1.f : 0.f,
                                  (k1c == lb1) ? 1.f : 0.f };
                    *(float2*)(Lab + (size_t)r0 * ldc + c) = l0;
                    *(float2*)(Lab + (size_t)r1 * ldc + c) = l1;
                }
            }
        }
    }
}

// ---------------- BN stats: per-feature scale/shift ----------------------
__global__ void bn_stats_k(const float* __restrict__ Hq, const float* __restrict__ Hk,
                           const float* __restrict__ gamma, const float* __restrict__ beta,
                           float* __restrict__ scq, float* __restrict__ shq,
                           float* __restrict__ sck, float* __restrict__ shk)
{
    const float* H = blockIdx.z ? Hk : Hq;
    float* scale = blockIdx.z ? sck : scq;
    float* shift = blockIdx.z ? shk : shq;
    int f = blockIdx.x * 32 + threadIdx.x;
    float s = 0.f, ss = 0.f;
    for (int r = threadIdx.y; r < Bsz; r += 32) {
        float v = H[(size_t)r * DF + f];
        s += v; ss += v * v;
    }
    __shared__ float sh_s[32][33], sh_ss[32][33];
    sh_s[threadIdx.y][threadIdx.x]  = s;
    sh_ss[threadIdx.y][threadIdx.x] = ss;
    __syncthreads();
    if (threadIdx.y == 0) {
        #pragma unroll
        for (int y = 1; y < 32; y++) {
            s += sh_s[y][threadIdx.x]; ss += sh_ss[y][threadIdx.x];
        }
        float mu  = s * (1.f / Bsz);
        float var = ss * (1.f / Bsz) - mu * mu;
        float rst = rsqrtf(var + 1e-5f);
        float scv = rst * gamma[f];
        scale[f] = scv;
        shift[f] = beta[f] - mu * scv;
    }
}

// ---------------- split-K reduce + bias + row l2norm ----------------------
__global__ void reduce_l2_k(const float* __restrict__ b2)
{
    int qk = blockIdx.y, b = blockIdx.x, d = threadIdx.x;  // d: 0..127
    const float* part = g_fpart + (size_t)qk * SPLITK * Bsz * DIM;
    float v = b2[d];
    #pragma unroll
    for (int s = 0; s < SPLITK; s++)
        v += part[(size_t)s * Bsz * DIM + (size_t)b * DIM + d];
    float ss = v * v;
    #pragma unroll
    for (int o = 16; o; o >>= 1) ss += __shfl_xor_sync(0xffffffffu, ss, o);
    __shared__ float ws[4];
    if ((d & 31) == 0) ws[d >> 5] = ss;
    __syncthreads();
    ss = ws[0] + ws[1] + ws[2] + ws[3];
    float inv = 1.f / fmaxf(sqrtf(ss), 1e-12f);
    float* dst = qk ? g_featk : g_featq;
    dst[(size_t)b * DIM + d] = v * inv;
}

// ---------------- pos_list: 8 dots + ones into labels ---------------------
__global__ void pos_k(const int* __restrict__ lq, const float* __restrict__ posq,
                      float* __restrict__ out)
{
    int b = blockIdx.x, tid = threadIdx.x;
    __shared__ float fr[DIM];
    if (tid < DIM) fr[tid] = g_featq[(size_t)b * DIM + tid];
    __syncthreads();
    int w = tid >> 5, lane = tid & 31;
    int col = lq[b] * PP + w;
    float s = 0.f;
    for (int d = lane; d < DIM; d += 32)
        s += fr[d] * posq[(size_t)d * PC + col];
    #pragma unroll
    for (int o = 16; o; o >>= 1) s += __shfl_down_sync(0xffffffffu, s, o);
    if (lane == 0) {
        out[OFF_SIM + (size_t)b * SIMW + Bsz + w] = s;
        out[OFF_LAB + (size_t)b * SIMW + Bsz + w] = 1.f;
    }
}

// ---------------- occurrence rank + count (warp-per-row) ------------------
__global__ void rank_k(const int* __restrict__ lk)
{
    __shared__ int sl[Bsz];
    int t = threadIdx.y * 32 + threadIdx.x;
    for (int i = t; i < Bsz; i += 1024) sl[i] = lk[i];
    __syncthreads();
    int b = blockIdx.x * 32 + threadIdx.y;
    int lab = sl[b];
    int r = 0, c = 0;
    for (int j = threadIdx.x; j < Bsz; j += 32) {
        int e = (sl[j] == lab);
        c += e;
        r += e & (j < b);
    }
    #pragma unroll
    for (int o = 16; o; o >>= 1) {
        c += __shfl_down_sync(0xffffffffu, c, o);
        r += __shfl_down_sync(0xffffffffu, r, o);
    }
    if (threadIdx.x == 0) { g_rank[b] = r; g_cntb[b] = c; }
}

// ---------------- ptr outputs (warp-per-class) -----------------------------
__global__ void ptr_k(const int* __restrict__ lk, const int* __restrict__ nptr,
                      const int* __restrict__ pptr, float* __restrict__ out)
{
    __shared__ int sl[Bsz];
    for (int i = threadIdx.x; i < Bsz; i += 256) sl[i] = lk[i];
    __syncthreads();
    int w = threadIdx.x >> 5, lane = threadIdx.x & 31;
    int c = blockIdx.x * 8 + w;
    int cnt = 0;
    for (int j = lane; j < Bsz; j += 32) cnt += (sl[j] == c);
    #pragma unroll
    for (int o = 16; o; o >>= 1) cnt += __shfl_down_sync(0xffffffffu, cnt, o);
    if (lane == 0) {
        out[OFF_NPTR + c] = (float)((nptr[c] + cnt) % NNq);
        out[OFF_PPTR + c] = (float)((pptr[c] + cnt) % PP);
    }
}

// ---------------- queue overwrite: survivors only ------------------------
__global__ void queue_update_k(const int* __restrict__ lk, const int* __restrict__ nptr,
                               const int* __restrict__ pptr, float* __restrict__ out)
{
    int b = blockIdx.x;
    int d = threadIdx.x;   // 128
    int lab = lk[b];
    int r = g_rank[b];
    int c = g_cntb[b];
    float v = g_featk[(size_t)b * DIM + d];
    if (r >= c - NNq) {
        int slot = (nptr[lab] + r) % NNq;
        out[OFF_NQ2 + (size_t)d * NC + lab * NNq + slot] = v;
    }
    if (r >= c - PP) {
        int slot = (pptr[lab] + r) % PP;
        out[OFF_PQ2 + (size_t)d * PC + lab * PP + slot] = v;
    }
}

// ---------------- host launcher -------------------------------------------
static float* symf(const void* sym) {
    void* p = nullptr;
    cudaGetSymbolAddress(&p, sym);
    return (float*)p;
}

extern "C" void kernel_launch(void* const* d_in, const int* in_sizes, int n_in,
                              void* d_out, int out_size)
{
    (void)in_sizes; (void)n_in; (void)out_size;
    const float* midq  = (const float*)d_in[0];
    const float* midk  = (const float*)d_in[1];
    const int*   lq    = (const int*)d_in[2];
    const int*   lk    = (const int*)d_in[3];
    const float* W1    = (const float*)d_in[4];
    const float* b1    = (const float*)d_in[5];
    const float* gamma = (const float*)d_in[6];
    const float* beta  = (const float*)d_in[7];
    const float* W2    = (const float*)d_in[8];
    const float* b2    = (const float*)d_in[9];
    const float* Wlin  = (const float*)d_in[10];
    const float* blin  = (const float*)d_in[11];
    const float* negq  = (const float*)d_in[12];
    const float* posq  = (const float*)d_in[13];
    const int*   nptr  = (const int*)d_in[14];
    const int*   pptr  = (const int*)d_in[15];
    float* out = (float*)d_out;

    float* Hq  = symf(g_Hq);
    float* Hk  = symf(g_Hk);
    float* scq = symf(g_scq); float* shq = symf(g_shq);
    float* sck = symf(g_sck); float* shk = symf(g_shk);
    float* fq  = symf(g_featq);
    float* fk  = symf(g_featk);
    float* fpart = symf(g_fpart);

    // copy queues to output (updates overwrite below)
    cudaMemcpyAsync(out + OFF_NQ2, negq, sizeof(float) * (size_t)DIM * NC,
                    cudaMemcpyDeviceToDevice);
    cudaMemcpyAsync(out + OFF_PQ2, posq, sizeof(float) * (size_t)DIM * PC,
                    cudaMemcpyDeviceToDevice);

    // logits: mid @ Wlin + blin (independent — big, launch early)
    tgemm_k<0><<<dim3(CC / 128, Bsz / 128, 2), 256>>>(
        midq, midk, Wlin, blin, out + OFF_LQ, out + OFF_LK,
        DF, DF, CC, CC, nullptr, nullptr, nullptr, nullptr,
        nullptr, nullptr, nullptr);

    // H = mid @ W1 + b1 (q and k batched via z)
    tgemm_k<0><<<dim3(DF / 128, Bsz / 128, 2), 256>>>(
        midq, midk, W1, b1, Hq, Hk,
        DF, DF, DF, DF, nullptr, nullptr, nullptr, nullptr,
        nullptr, nullptr, nullptr);

    // BN affine params (q and k batched via z)
    bn_stats_k<<<dim3(DF / 32, 1, 2), dim3(32, 32)>>>(
        Hq, Hk, gamma, beta, scq, shq, sck, shk);

    // feat partials = relu(BN(H)) @ W2 (split-K=16, q/k via z)
    tgemm_k<2><<<dim3(1, Bsz / 128, 2 * SPLITK), 256>>>(
        Hq, Hk, W2, nullptr, fpart, nullptr,
        DF, DF, DIM, DIM, scq, shq, sck, shk, nullptr, nullptr, nullptr);

    // reduce partials + bias + l2norm
    reduce_l2_k<<<dim3(Bsz, 2), DIM>>>(b2);

    // sim_batch = feat_q @ feat_k^T  (+ labels_batch fused)
    tgemm_k<3><<<dim3(Bsz / 128, Bsz / 128, 1), 256>>>(
        fq, nullptr, fk, nullptr, out + OFF_SIM, nullptr,
        DIM, DIM, DIM, SIMW, nullptr, nullptr, nullptr, nullptr,
        lq, lk, out + OFF_LAB);

    // pos_list into sim_con[:, B:B+P] (+ ones into labels)
    pos_k<<<Bsz, 256>>>(lq, posq, out);

    // neg gathered into sim_con[:, B+P:] (+ zeros into labels)
    tgemm_k<4><<<dim3(NC / 128, Bsz / 128, 1), 256>>>(
        fq, nullptr, negq, nullptr, out + OFF_SIM + Bsz + PP, nullptr,
        DIM, DIM, NC, SIMW, nullptr, nullptr, nullptr, nullptr,
        lq, nullptr, out + OFF_LAB + Bsz + PP);

    // queue update machinery
    rank_k<<<32, dim3(32, 32)>>>(lk);
    ptr_k<<<CC / 8, 256>>>(lk, nptr, pptr, out);
    queue_update_k<<<Bsz, DIM>>>(lk, nptr, pptr, out);
}

// round 9
// speedup vs baseline: 1.3880x; 1.2377x over previous
#include <cuda_runtime.h>
#include <cuda_fp16.h>
#include <cstddef>
#include <cstdint>

#define Bsz   1024
#define DF    2048
#define DIM   128
#define CC    8192
#define PP    8
#define NNq   4
#define NC    (NNq * CC)            // 32768
#define PC    (PP * CC)             // 65536
#define SIMW  (Bsz + PP + NNq * (CC - 1))  // 33796
#define SPLITK 16

static constexpr size_t OFF_SIM  = 0;
static constexpr size_t OFF_LAB  = (size_t)Bsz * SIMW;
static constexpr size_t OFF_LQ   = OFF_LAB + (size_t)Bsz * SIMW;
static constexpr size_t OFF_LK   = OFF_LQ + (size_t)Bsz * CC;
static constexpr size_t OFF_NQ2  = OFF_LK + (size_t)Bsz * CC;
static constexpr size_t OFF_PQ2  = OFF_NQ2 + (size_t)DIM * NC;
static constexpr size_t OFF_NPTR = OFF_PQ2 + (size_t)DIM * PC;
static constexpr size_t OFF_PPTR = OFF_NPTR + CC;

// ---------------- device scratch (16B-aligned for cp.async) ---------------
__device__ __align__(16) float  g_Hq[(size_t)Bsz * DF];
__device__ __align__(16) float  g_Hk[(size_t)Bsz * DF];
__device__ __align__(16) __half g_midqH[(size_t)Bsz * DF];
__device__ __align__(16) __half g_midkH[(size_t)Bsz * DF];
__device__ __align__(16) __half g_HqH[(size_t)Bsz * DF];     // relu(BN(H)) half
__device__ __align__(16) __half g_HkH[(size_t)Bsz * DF];
__device__ __align__(16) __half g_W1T[(size_t)DF * DF];      // [N][K] half
__device__ __align__(16) __half g_WlinT[(size_t)CC * DF];
__device__ __align__(16) __half g_W2T[(size_t)DIM * DF];
__device__ __align__(16) __half g_negT[(size_t)NC * DIM];
__device__ float g_scq[DF], g_shq[DF], g_sck[DF], g_shk[DF];
__device__ float g_featq[(size_t)Bsz * DIM];
__device__ float g_featk[(size_t)Bsz * DIM];
__device__ __align__(16) __half g_featqH[(size_t)Bsz * DIM];
__device__ __align__(16) __half g_featkH[(size_t)Bsz * DIM];
__device__ float g_fpart[(size_t)2 * SPLITK * Bsz * DIM];
__device__ int   g_rank[Bsz];
__device__ int   g_cntb[Bsz];

// ---------------- helpers -------------------------------------------------
__device__ __forceinline__ void mma_f16(float c[4], const unsigned a[4],
                                        const unsigned b[2]) {
    asm volatile(
        "mma.sync.aligned.m16n8k16.row.col.f32.f16.f16.f32 "
        "{%0,%1,%2,%3}, {%4,%5,%6,%7}, {%8,%9}, {%0,%1,%2,%3};"
        : "+f"(c[0]), "+f"(c[1]), "+f"(c[2]), "+f"(c[3])
        : "r"(a[0]), "r"(a[1]), "r"(a[2]), "r"(a[3]), "r"(b[0]), "r"(b[1]));
}

__device__ __forceinline__ void cpa16(uint32_t saddr, const void* g) {
    asm volatile("cp.async.cg.shared.global [%0], [%1], 16;\n"
                 :: "r"(saddr), "l"(g));
}
#define CP_COMMIT() asm volatile("cp.async.commit_group;\n" ::: "memory")
#define CP_WAIT1()  asm volatile("cp.async.wait_group 1;\n" ::: "memory")
#define CP_WAIT0()  asm volatile("cp.async.wait_group 0;\n" ::: "memory")

// ---------------- FP16 tensor-core GEMM, cp.async double-buffered ---------
// 128x128 tile, BK=32 (halfs), 256 threads (8 warps, warp tile 64x32).
// A [M][K] half, Bt [N][K] half (both K-major; shared staging path).
// Smem rows of 40 halfs (=20 words): fragment .b32 banks 20g+tig, conflict-
// free (identical bank set to the proven ASTR=20 fp32 layout).
// MODE 0: C = A@B + bias; z selects (A0,C0)/(A1,C1)
// MODE 2: split-K partial: z = qk*SPLITK + sk; C = C0 + z*Bsz*DIM
// MODE 3: plain; also writes labels_batch (lkk[n]==lqq[m]) into Lab
// MODE 4: neg scatter skipping lqq[m]'s NNq cols; writes 0.0f into Lab
#define HSTR 40
template <int MODE>
__global__ __launch_bounds__(256, 2) void hgemm_k(
    const __half* __restrict__ A0, const __half* __restrict__ A1,
    const __half* __restrict__ Bt, const float* __restrict__ bias,
    float* __restrict__ C0, float* __restrict__ C1,
    int K, int ldc,
    const int* __restrict__ lqq, const int* __restrict__ lkk,
    float* __restrict__ Lab)
{
    __shared__ __align__(16) __half As[2][128 * HSTR];
    __shared__ __align__(16) __half Bs[2][128 * HSTR];

    const int tid   = threadIdx.x;
    const int mBase = blockIdx.y * 128;
    const int nBase = blockIdx.x * 128;
    const int lane  = tid & 31;
    const int warp  = tid >> 5;
    const int g     = lane >> 2;
    const int tig   = lane & 3;
    const int wm    = (warp & 1) * 64;
    const int wn    = (warp >> 1) * 32;

    int kBeg = 0, kEnd = K;
    const __half* A;
    float* Cc;
    if (MODE == 2) {
        int qk  = blockIdx.z >> 4;
        int skc = blockIdx.z & 15;
        kBeg = skc * (K / SPLITK);
        kEnd = kBeg + K / SPLITK;
        A  = qk ? A1 : A0;
        Cc = C0 + (size_t)blockIdx.z * ((size_t)Bsz * DIM);
    } else {
        A  = blockIdx.z ? A1 : A0;
        Cc = blockIdx.z ? C1 : C0;
    }

    uint32_t asA = (uint32_t)__cvta_generic_to_shared(&As[0][0]);
    uint32_t asB = (uint32_t)__cvta_generic_to_shared(&Bs[0][0]);

    // staging: each row = 32 halfs = 4 x 16B chunks; 2 threads/row, 2 chunks each
    const int sr = tid >> 1;
    const int cb = (tid & 1) * 2;
    auto load_tiles = [&](int s, int kpos) {
        const __half* srcA = A  + (size_t)(mBase + sr) * K + kpos;
        const __half* srcB = Bt + (size_t)(nBase + sr) * K + kpos;
        #pragma unroll
        for (int i = 0; i < 2; i++) {
            int c = cb + i;
            cpa16(asA + (uint32_t)((s * 128 * HSTR + sr * HSTR + c * 8) * 2),
                  srcA + c * 8);
            cpa16(asB + (uint32_t)((s * 128 * HSTR + sr * HSTR + c * 8) * 2),
                  srcB + c * 8);
        }
    };

    float acc[4][4][4] = {};

    const int nIter = (kEnd - kBeg) / 32;
    load_tiles(0, kBeg);
    CP_COMMIT();

    for (int it = 0; it < nIter; ++it) {
        int s = it & 1;
        if (it + 1 < nIter) {
            load_tiles(s ^ 1, kBeg + (it + 1) * 32);
            CP_COMMIT();
            CP_WAIT1();
        } else {
            CP_WAIT0();
        }
        __syncthreads();

        const __half* as = As[s];
        const __half* bs = Bs[s];
        #pragma unroll
        for (int kk = 0; kk < 32; kk += 16) {
            unsigned af[4][4], bf[4][2];
            const int ka = kk + 2 * tig;
            #pragma unroll
            for (int mt = 0; mt < 4; mt++) {
                int mr = wm + mt * 16 + g;
                af[mt][0] = *(const unsigned*)(as + mr * HSTR + ka);
                af[mt][1] = *(const unsigned*)(as + (mr + 8) * HSTR + ka);
                af[mt][2] = *(const unsigned*)(as + mr * HSTR + ka + 8);
                af[mt][3] = *(const unsigned*)(as + (mr + 8) * HSTR + ka + 8);
            }
            #pragma unroll
            for (int nt = 0; nt < 4; nt++) {
                int nc = wn + nt * 8 + g;
                bf[nt][0] = *(const unsigned*)(bs + nc * HSTR + ka);
                bf[nt][1] = *(const unsigned*)(bs + nc * HSTR + ka + 8);
            }
            #pragma unroll
            for (int mt = 0; mt < 4; mt++)
                #pragma unroll
                for (int nt = 0; nt < 4; nt++)
                    mma_f16(acc[mt][nt], af[mt], bf[nt]);
        }
        __syncthreads();
    }

    // ---- epilogue ----
    #pragma unroll
    for (int mt = 0; mt < 4; mt++) {
        int r0 = mBase + wm + mt * 16 + g;
        int r1 = r0 + 8;
        int la0 = 0, la1 = 0, lb0 = 0, lb1 = 0;
        if (MODE == 4) { la0 = lqq[r0] * NNq; la1 = lqq[r1] * NNq; }
        if (MODE == 3) { lb0 = lqq[r0]; lb1 = lqq[r1]; }
        #pragma unroll
        for (int nt = 0; nt < 4; nt++) {
            int c = nBase + wn + nt * 8 + 2 * tig;
            const float* a4 = acc[mt][nt];
            if (MODE == 4) {
                int n0 = c, n1 = c + 1;
                if (n0 < la0) {
                    Cc [(size_t)r0 * ldc + n0] = a4[0];
                    Lab[(size_t)r0 * ldc + n0] = 0.f;
                } else if (n0 >= la0 + NNq) {
                    Cc [(size_t)r0 * ldc + n0 - NNq] = a4[0];
                    Lab[(size_t)r0 * ldc + n0 - NNq] = 0.f;
                }
                if (n1 < la0) {
                    Cc [(size_t)r0 * ldc + n1] = a4[1];
                    Lab[(size_t)r0 * ldc + n1] = 0.f;
                } else if (n1 >= la0 + NNq) {
                    Cc [(size_t)r0 * ldc + n1 - NNq] = a4[1];
                    Lab[(size_t)r0 * ldc + n1 - NNq] = 0.f;
                }
                if (n0 < la1) {
                    Cc [(size_t)r1 * ldc + n0] = a4[2];
                    Lab[(size_t)r1 * ldc + n0] = 0.f;
                } else if (n0 >= la1 + NNq) {
                    Cc [(size_t)r1 * ldc + n0 - NNq] = a4[2];
                    Lab[(size_t)r1 * ldc + n0 - NNq] = 0.f;
                }
                if (n1 < la1) {
                    Cc [(size_t)r1 * ldc + n1] = a4[3];
                    Lab[(size_t)r1 * ldc + n1] = 0.f;
                } else if (n1 >= la1 + NNq) {
                    Cc [(size_t)r1 * ldc + n1 - NNq] = a4[3];
                    Lab[(size_t)r1 * ldc + n1 - NNq] = 0.f;
                }
            } else {
                float bx = 0.f, by = 0.f;
                if (MODE == 0) { bx = bias[c]; by = bias[c + 1]; }
                float2 v0 = { a4[0] + bx, a4[1] + by };
                float2 v1 = { a4[2] + bx, a4[3] + by };
                *(float2*)(Cc + (size_t)r0 * ldc + c) = v0;
                *(float2*)(Cc + (size_t)r1 * ldc + c) = v1;
                if (MODE == 3) {
                    int k0c = lkk[c], k1c = lkk[c + 1];
                    float2 l0 = { (k0c == lb0) ? 1.f : 0.f,
                                  (k1c == lb0) ? 1.f : 0.f };
                    float2 l1 = { (k0c == lb1) ? 1.f : 0.f,
                                  (k1c == lb1) ? 1.f : 0.f };
                    *(float2*)(Lab + (size_t)r0 * ldc + c) = l0;
                    *(float2*)(Lab + (size_t)r1 * ldc + c) = l1;
                }
            }
        }
    }
}

// ---------------- prep: fp32 -> fp16 (8 / thread; q/k via z) ---------------
__global__ void cvt_half_k(const float* __restrict__ in0, const float* __restrict__ in1,
                           __half* __restrict__ o0, __half* __restrict__ o1, int n8)
{
    const float* in = blockIdx.z ? in1 : in0;
    __half* o = blockIdx.z ? o1 : o0;
    int i = blockIdx.x * blockDim.x + threadIdx.x;
    if (i >= n8) return;
    float4 a = ((const float4*)in)[i * 2];
    float4 b = ((const float4*)in)[i * 2 + 1];
    __half h[8];
    h[0] = __float2half_rn(a.x); h[1] = __float2half_rn(a.y);
    h[2] = __float2half_rn(a.z); h[3] = __float2half_rn(a.w);
    h[4] = __float2half_rn(b.x); h[5] = __float2half_rn(b.y);
    h[6] = __float2half_rn(b.z); h[7] = __float2half_rn(b.w);
    ((uint4*)o)[i] = *(const uint4*)h;
}

// ---------------- prep: transpose fp32 [R][C] -> half [C][R] ---------------
__global__ void transpose_half_k(const float* __restrict__ in, __half* __restrict__ out,
                                 int R, int C)
{
    __shared__ float t[32][33];
    int cx = blockIdx.x * 32 + threadIdx.x;
    int ry = blockIdx.y * 32 + threadIdx.y;
    #pragma unroll
    for (int j = 0; j < 32; j += 8)
        t[threadIdx.y + j][threadIdx.x] = in[(size_t)(ry + j) * C + cx];
    __syncthreads();
    int cx2 = blockIdx.y * 32 + threadIdx.x;
    int ry2 = blockIdx.x * 32 + threadIdx.y;
    #pragma unroll
    for (int j = 0; j < 32; j += 8)
        out[(size_t)(ry2 + j) * R + cx2] = __float2half_rn(t[threadIdx.x][threadIdx.y + j]);
}

// ---------------- BN stats -------------------------------------------------
__global__ void bn_stats_k(const float* __restrict__ Hq, const float* __restrict__ Hk,
                           const float* __restrict__ gamma, const float* __restrict__ beta,
                           float* __restrict__ scq, float* __restrict__ shq,
                           float* __restrict__ sck, float* __restrict__ shk)
{
    const float* H = blockIdx.z ? Hk : Hq;
    float* scale = blockIdx.z ? sck : scq;
    float* shift = blockIdx.z ? shk : shq;
    int f = blockIdx.x * 32 + threadIdx.x;
    float s = 0.f, ss = 0.f;
    for (int r = threadIdx.y; r < Bsz; r += 32) {
        float v = H[(size_t)r * DF + f];
        s += v; ss += v * v;
    }
    __shared__ float sh_s[32][33], sh_ss[32][33];
    sh_s[threadIdx.y][threadIdx.x]  = s;
    sh_ss[threadIdx.y][threadIdx.x] = ss;
    __syncthreads();
    if (threadIdx.y == 0) {
        #pragma unroll
        for (int y = 1; y < 32; y++) {
            s += sh_s[y][threadIdx.x]; ss += sh_ss[y][threadIdx.x];
        }
        float mu  = s * (1.f / Bsz);
        float var = ss * (1.f / Bsz) - mu * mu;
        float rst = rsqrtf(var + 1e-5f);
        float scv = rst * gamma[f];
        scale[f] = scv;
        shift[f] = beta[f] - mu * scv;
    }
}

// ---------------- BN apply + relu -> half ----------------------------------
__global__ void bnrelu_half_k(const float* __restrict__ Hq, const float* __restrict__ Hk,
                              __half* __restrict__ Rq, __half* __restrict__ Rk)
{
    const float* H = blockIdx.z ? Hk : Hq;
    __half* R = blockIdx.z ? Rk : Rq;
    const float* sc = blockIdx.z ? g_sck : g_scq;
    const float* sh = blockIdx.z ? g_shk : g_shq;
    int i = blockIdx.x * blockDim.x + threadIdx.x;   // 8-float group
    int f = (i * 8) & (DF - 1);
    float4 a = ((const float4*)H)[i * 2];
    float4 b = ((const float4*)H)[i * 2 + 1];
    float4 sa = *(const float4*)(sc + f);
    float4 sb = *(const float4*)(sc + f + 4);
    float4 ha = *(const float4*)(sh + f);
    float4 hb = *(const float4*)(sh + f + 4);
    __half h[8];
    h[0] = __float2half_rn(fmaxf(fmaf(a.x, sa.x, ha.x), 0.f));
    h[1] = __float2half_rn(fmaxf(fmaf(a.y, sa.y, ha.y), 0.f));
    h[2] = __float2half_rn(fmaxf(fmaf(a.z, sa.z, ha.z), 0.f));
    h[3] = __float2half_rn(fmaxf(fmaf(a.w, sa.w, ha.w), 0.f));
    h[4] = __float2half_rn(fmaxf(fmaf(b.x, sb.x, hb.x), 0.f));
    h[5] = __float2half_rn(fmaxf(fmaf(b.y, sb.y, hb.y), 0.f));
    h[6] = __float2half_rn(fmaxf(fmaf(b.z, sb.z, hb.z), 0.f));
    h[7] = __float2half_rn(fmaxf(fmaf(b.w, sb.w, hb.w), 0.f));
    ((uint4*)R)[i] = *(const uint4*)h;
}

// ---------------- split-K reduce + bias + l2norm ---------------------------
__global__ void reduce_l2_k(const float* __restrict__ b2)
{
    int qk = blockIdx.y, b = blockIdx.x, d = threadIdx.x;  // d: 0..127
    const float* part = g_fpart + (size_t)qk * SPLITK * Bsz * DIM;
    float v = b2[d];
    #pragma unroll
    for (int s = 0; s < SPLITK; s++)
        v += part[(size_t)s * Bsz * DIM + (size_t)b * DIM + d];
    float ss = v * v;
    #pragma unroll
    for (int o = 16; o; o >>= 1) ss += __shfl_xor_sync(0xffffffffu, ss, o);
    __shared__ float ws[4];
    if ((d & 31) == 0) ws[d >> 5] = ss;
    __syncthreads();
    ss = ws[0] + ws[1] + ws[2] + ws[3];
    float inv = 1.f / fmaxf(sqrtf(ss), 1e-12f);
    float vn = v * inv;
    if (qk) {
        g_featk[(size_t)b * DIM + d] = vn;
        g_featkH[(size_t)b * DIM + d] = __float2half_rn(vn);
    } else {
        g_featq[(size_t)b * DIM + d] = vn;
        g_featqH[(size_t)b * DIM + d] = __float2half_rn(vn);
    }
}

// ---------------- pos_list (+ ones into labels) ----------------------------
__global__ void pos_k(const int* __restrict__ lq, const float* __restrict__ posq,
                      float* __restrict__ out)
{
    int b = blockIdx.x, tid = threadIdx.x;
    __shared__ float fr[DIM];
    if (tid < DIM) fr[tid] = g_featq[(size_t)b * DIM + tid];
    __syncthreads();
    int w = tid >> 5, lane = tid & 31;
    int col = lq[b] * PP + w;
    float s = 0.f;
    for (int d = lane; d < DIM; d += 32)
        s += fr[d] * posq[(size_t)d * PC + col];
    #pragma unroll
    for (int o = 16; o; o >>= 1) s += __shfl_down_sync(0xffffffffu, s, o);
    if (lane == 0) {
        out[OFF_SIM + (size_t)b * SIMW + Bsz + w] = s;
        out[OFF_LAB + (size_t)b * SIMW + Bsz + w] = 1.f;
    }
}

// ---------------- occurrence rank + count (warp-per-row) -------------------
__global__ void rank_k(const int* __restrict__ lk)
{
    __shared__ int sl[Bsz];
    int t = threadIdx.y * 32 + threadIdx.x;
    for (int i = t; i < Bsz; i += 1024) sl[i] = lk[i];
    __syncthreads();
    int b = blockIdx.x * 32 + threadIdx.y;
    int lab = sl[b];
    int r = 0, c = 0;
    for (int j = threadIdx.x; j < Bsz; j += 32) {
        int e = (sl[j] == lab);
        c += e;
        r += e & (j < b);
    }
    #pragma unroll
    for (int o = 16; o; o >>= 1) {
        c += __shfl_down_sync(0xffffffffu, c, o);
        r += __shfl_down_sync(0xffffffffu, r, o);
    }
    if (threadIdx.x == 0) { g_rank[b] = r; g_cntb[b] = c; }
}

// ---------------- ptr outputs (warp-per-class) -----------------------------
__global__ void ptr_k(const int* __restrict__ lk, const int* __restrict__ nptr,
                      const int* __restrict__ pptr, float* __restrict__ out)
{
    __shared__ int sl[Bsz];
    for (int i = threadIdx.x; i < Bsz; i += 256) sl[i] = lk[i];
    __syncthreads();
    int w = threadIdx.x >> 5, lane = threadIdx.x & 31;
    int c = blockIdx.x * 8 + w;
    int cnt = 0;
    for (int j = lane; j < Bsz; j += 32) cnt += (sl[j] == c);
    #pragma unroll
    for (int o = 16; o; o >>= 1) cnt += __shfl_down_sync(0xffffffffu, cnt, o);
    if (lane == 0) {
        out[OFF_NPTR + c] = (float)((nptr[c] + cnt) % NNq);
        out[OFF_PPTR + c] = (float)((pptr[c] + cnt) % PP);
    }
}

// ---------------- queue overwrite ------------------------------------------
__global__ void queue_update_k(const int* __restrict__ lk, const int* __restrict__ nptr,
                               const int* __restrict__ pptr, float* __restrict__ out)
{
    int b = blockIdx.x;
    int d = threadIdx.x;   // 128
    int lab = lk[b];
    int r = g_rank[b];
    int c = g_cntb[b];
    float v = g_featk[(size_t)b * DIM + d];
    if (r >= c - NNq) {
        int slot = (nptr[lab] + r) % NNq;
        out[OFF_NQ2 + (size_t)d * NC + lab * NNq + slot] = v;
    }
    if (r >= c - PP) {
        int slot = (pptr[lab] + r) % PP;
        out[OFF_PQ2 + (size_t)d * PC + lab * PP + slot] = v;
    }
}

// ---------------- host launcher --------------------------------------------
static void* symp(const void* sym) {
    void* p = nullptr;
    cudaGetSymbolAddress(&p, sym);
    return p;
}

extern "C" void kernel_launch(void* const* d_in, const int* in_sizes, int n_in,
                              void* d_out, int out_size)
{
    (void)in_sizes; (void)n_in; (void)out_size;
    const float* midq  = (const float*)d_in[0];
    const float* midk  = (const float*)d_in[1];
    const int*   lq    = (const int*)d_in[2];
    const int*   lk    = (const int*)d_in[3];
    const float* W1    = (const float*)d_in[4];
    const float* b1    = (const float*)d_in[5];
    const float* gamma = (const float*)d_in[6];
    const float* beta  = (const float*)d_in[7];
    const float* W2    = (const float*)d_in[8];
    const float* b2    = (const float*)d_in[9];
    const float* Wlin  = (const float*)d_in[10];
    const float* blin  = (const float*)d_in[11];
    const float* negq  = (const float*)d_in[12];
    const float* posq  = (const float*)d_in[13];
    const int*   nptr  = (const int*)d_in[14];
    const int*   pptr  = (const int*)d_in[15];
    float* out = (float*)d_out;

    float*  Hq     = (float*)symp(g_Hq);
    float*  Hk     = (float*)symp(g_Hk);
    __half* midqH  = (__half*)symp(g_midqH);
    __half* midkH  = (__half*)symp(g_midkH);
    __half* HqH    = (__half*)symp(g_HqH);
    __half* HkH    = (__half*)symp(g_HkH);
    __half* W1T    = (__half*)symp(g_W1T);
    __half* WlinT  = (__half*)symp(g_WlinT);
    __half* W2T    = (__half*)symp(g_W2T);
    __half* negT   = (__half*)symp(g_negT);
    float*  scq = (float*)symp(g_scq); float* shq = (float*)symp(g_shq);
    float*  sck = (float*)symp(g_sck); float* shk = (float*)symp(g_shk);
    __half* fqH = (__half*)symp(g_featqH);
    __half* fkH = (__half*)symp(g_featkH);
    float*  fpart = (float*)symp(g_fpart);

    // queues copied to output (queue_update overwrites survivors)
    cudaMemcpyAsync(out + OFF_NQ2, negq, sizeof(float) * (size_t)DIM * NC,
                    cudaMemcpyDeviceToDevice);
    cudaMemcpyAsync(out + OFF_PQ2, posq, sizeof(float) * (size_t)DIM * PC,
                    cudaMemcpyDeviceToDevice);

    // ---- prep: convert activations; transpose+convert weights ----
    cvt_half_k<<<dim3(Bsz * DF / 8 / 256, 1, 2), 256>>>(
        midq, midk, midqH, midkH, Bsz * DF / 8);
    transpose_half_k<<<dim3(CC / 32, DF / 32), dim3(32, 8)>>>(Wlin, WlinT, DF, CC);
    transpose_half_k<<<dim3(DF / 32, DF / 32), dim3(32, 8)>>>(W1, W1T, DF, DF);
    transpose_half_k<<<dim3(DIM / 32, DF / 32), dim3(32, 8)>>>(W2, W2T, DF, DIM);
    transpose_half_k<<<dim3(NC / 32, DIM / 32), dim3(32, 8)>>>(negq, negT, DIM, NC);

    // ---- logits: mid @ Wlin + blin ----
    hgemm_k<0><<<dim3(CC / 128, Bsz / 128, 2), 256>>>(
        midqH, midkH, WlinT, blin, out + OFF_LQ, out + OFF_LK,
        DF, CC, nullptr, nullptr, nullptr);

    // ---- H = mid @ W1 + b1 ----
    hgemm_k<0><<<dim3(DF / 128, Bsz / 128, 2), 256>>>(
        midqH, midkH, W1T, b1, Hq, Hk, DF, DF, nullptr, nullptr, nullptr);

    // ---- BN stats + apply(relu) -> half ----
    bn_stats_k<<<dim3(DF / 32, 1, 2), dim3(32, 32)>>>(
        Hq, Hk, gamma, beta, scq, shq, sck, shk);
    bnrelu_half_k<<<dim3(Bsz * DF / 8 / 256, 1, 2), 256>>>(Hq, Hk, HqH, HkH);

    // ---- feat partials = relu(BN(H)) @ W2 (split-K 16, q/k via z) ----
    hgemm_k<2><<<dim3(1, Bsz / 128, 2 * SPLITK), 256>>>(
        HqH, HkH, W2T, nullptr, fpart, nullptr, DF, DIM,
        nullptr, nullptr, nullptr);

    // ---- reduce + bias + l2norm (fp32 + half feats) ----
    reduce_l2_k<<<dim3(Bsz, 2), DIM>>>(b2);

    // ---- sim_batch = feat_q @ feat_k^T (+ labels fused); featkH is [N][K] ----
    hgemm_k<3><<<dim3(Bsz / 128, Bsz / 128, 1), 256>>>(
        fqH, nullptr, fkH, nullptr, out + OFF_SIM, nullptr, DIM, SIMW,
        lq, lk, out + OFF_LAB);

    // ---- pos_list (+ ones) ----
    pos_k<<<Bsz, 256>>>(lq, posq, out);

    // ---- neg gathered (+ zeros into labels) ----
    hgemm_k<4><<<dim3(NC / 128, Bsz / 128, 1), 256>>>(
        fqH, nullptr, negT, nullptr, out + OFF_SIM + Bsz + PP, nullptr,
        DIM, SIMW, lq, nullptr, out + OFF_LAB + Bsz + PP);

    // ---- queue update ----
    rank_k<<<32, dim3(32, 32)>>>(lk);
    ptr_k<<<CC / 8, 256>>>(lk, nptr, pptr, out);
    queue_update_k<<<Bsz, DIM>>>(lk, nptr, pptr, out);
}

// round 11
// speedup vs baseline: 1.4191x; 1.0224x over previous
#include <cuda_runtime.h>
#include <cuda_fp16.h>
#include <cstddef>
#include <cstdint>

#define Bsz   1024
#define DF    2048
#define DIM   128
#define CC    8192
#define PP    8
#define NNq   4
#define NC    (NNq * CC)            // 32768
#define PC    (PP * CC)             // 65536
#define SIMW  (Bsz + PP + NNq * (CC - 1))  // 33796
#define SPLITK 16

static constexpr size_t OFF_SIM  = 0;
static constexpr size_t OFF_LAB  = (size_t)Bsz * SIMW;
static constexpr size_t OFF_LQ   = OFF_LAB + (size_t)Bsz * SIMW;
static constexpr size_t OFF_LK   = OFF_LQ + (size_t)Bsz * CC;
static constexpr size_t OFF_NQ2  = OFF_LK + (size_t)Bsz * CC;
static constexpr size_t OFF_PQ2  = OFF_NQ2 + (size_t)DIM * NC;
static constexpr size_t OFF_NPTR = OFF_PQ2 + (size_t)DIM * PC;
static constexpr size_t OFF_PPTR = OFF_NPTR + CC;

// ---------------- device scratch (16B-aligned for cp.async) ---------------
__device__ __align__(16) float  g_Hq[(size_t)Bsz * DF];
__device__ __align__(16) float  g_Hk[(size_t)Bsz * DF];
__device__ __align__(16) __half g_midqH[(size_t)Bsz * DF];
__device__ __align__(16) __half g_midkH[(size_t)Bsz * DF];
__device__ __align__(16) __half g_HqH[(size_t)Bsz * DF];     // relu(BN(H)) half
__device__ __align__(16) __half g_HkH[(size_t)Bsz * DF];
__device__ __align__(16) __half g_W1T[(size_t)DF * DF];      // [N][K] half
__device__ __align__(16) __half g_WlinT[(size_t)CC * DF];
__device__ __align__(16) __half g_W2T[(size_t)DIM * DF];
__device__ __align__(16) __half g_negT[(size_t)NC * DIM];
__device__ float g_scq[DF], g_shq[DF], g_sck[DF], g_shk[DF];
__device__ float g_featq[(size_t)Bsz * DIM];
__device__ float g_featk[(size_t)Bsz * DIM];
__device__ __align__(16) __half g_featqH[(size_t)Bsz * DIM];
__device__ __align__(16) __half g_featkH[(size_t)Bsz * DIM];
__device__ float g_fpart[(size_t)2 * SPLITK * Bsz * DIM];
__device__ int   g_rank[Bsz];
__device__ int   g_cntb[Bsz];

// ---------------- helpers -------------------------------------------------
__device__ __forceinline__ void mma_f16(float c[4], const unsigned a[4],
                                        const unsigned b[2]) {
    asm volatile(
        "mma.sync.aligned.m16n8k16.row.col.f32.f16.f16.f32 "
        "{%0,%1,%2,%3}, {%4,%5,%6,%7}, {%8,%9}, {%0,%1,%2,%3};"
        : "+f"(c[0]), "+f"(c[1]), "+f"(c[2]), "+f"(c[3])
        : "r"(a[0]), "r"(a[1]), "r"(a[2]), "r"(a[3]), "r"(b[0]), "r"(b[1]));
}

__device__ __forceinline__ void ldsm_x4(unsigned r[4], uint32_t addr) {
    asm volatile("ldmatrix.sync.aligned.m8n8.x4.shared.b16 {%0,%1,%2,%3}, [%4];"
                 : "=r"(r[0]), "=r"(r[1]), "=r"(r[2]), "=r"(r[3]) : "r"(addr));
}
// B stored [N][K]: mma b-frag wants stored(n=l>>2, k=2(l&3)+{0,1}) — the
// NON-trans ldmatrix mapping (R10's .trans was the correctness bug).
__device__ __forceinline__ void ldsm_x2(unsigned r[2], uint32_t addr) {
    asm volatile("ldmatrix.sync.aligned.m8n8.x2.shared.b16 {%0,%1}, [%2];"
                 : "=r"(r[0]), "=r"(r[1]) : "r"(addr));
}

__device__ __forceinline__ void cpa16(uint32_t saddr, const void* g) {
    asm volatile("cp.async.cg.shared.global [%0], [%1], 16;\n"
                 :: "r"(saddr), "l"(g));
}
#define CP_COMMIT() asm volatile("cp.async.commit_group;\n" ::: "memory")
#define CP_WAIT1()  asm volatile("cp.async.wait_group 1;\n" ::: "memory")
#define CP_WAIT0()  asm volatile("cp.async.wait_group 0;\n" ::: "memory")

// ---------------- FP16 tensor-core GEMM, cp.async double-buffered ---------
// 128x128 tile, BK=32 (halfs), 256 threads (8 warps, warp tile 64x32).
// A [M][K] half, Bt [N][K] half (K-major; shared staging path).
// Smem rows of 40 halfs (80B pitch): ldmatrix row banks 20r mod 32 —
// conflict-free; rows 16B-aligned.
// Fragments via ldmatrix.x4 (A) / ldmatrix.x2 non-trans (B).
// MODE 0: C = A@B + bias; z selects (A0,C0)/(A1,C1)
// MODE 2: split-K partial: z = qk*SPLITK + sk; C = C0 + z*Bsz*DIM
// MODE 3: plain; also writes labels_batch (lkk[n]==lqq[m]) into Lab
// MODE 4: neg scatter skipping lqq[m]'s NNq cols; writes 0.0f into Lab
#define HSTR 40
template <int MODE>
__global__ __launch_bounds__(256, 2) void hgemm_k(
    const __half* __restrict__ A0, const __half* __restrict__ A1,
    const __half* __restrict__ Bt, const float* __restrict__ bias,
    float* __restrict__ C0, float* __restrict__ C1,
    int K, int ldc,
    const int* __restrict__ lqq, const int* __restrict__ lkk,
    float* __restrict__ Lab)
{
    __shared__ __align__(16) __half As[2][128 * HSTR];
    __shared__ __align__(16) __half Bs[2][128 * HSTR];

    const int tid   = threadIdx.x;
    const int mBase = blockIdx.y * 128;
    const int nBase = blockIdx.x * 128;
    const int lane  = tid & 31;
    const int warp  = tid >> 5;
    const int g     = lane >> 2;
    const int tig   = lane & 3;
    const int wm    = (warp & 1) * 64;
    const int wn    = (warp >> 1) * 32;

    int kBeg = 0, kEnd = K;
    const __half* A;
    float* Cc;
    if (MODE == 2) {
        int qk  = blockIdx.z >> 4;
        int skc = blockIdx.z & 15;
        kBeg = skc * (K / SPLITK);
        kEnd = kBeg + K / SPLITK;
        A  = qk ? A1 : A0;
        Cc = C0 + (size_t)blockIdx.z * ((size_t)Bsz * DIM);
    } else {
        A  = blockIdx.z ? A1 : A0;
        Cc = blockIdx.z ? C1 : C0;
    }

    uint32_t asA = (uint32_t)__cvta_generic_to_shared(&As[0][0]);
    uint32_t asB = (uint32_t)__cvta_generic_to_shared(&Bs[0][0]);

    // ldmatrix per-lane address components
    const int a_row = wm + (lane & 7) + ((lane >> 3) & 1) * 8;  // + mt*16
    const int a_kof = (lane >> 4) << 3;                         // 0 or 8
    const int b_row = wn + (lane & 7);                          // + nt*8
    const int b_kof = ((lane >> 3) & 1) << 3;                   // 0 or 8

    // staging: each row = 32 halfs = 4 x 16B chunks; 2 threads/row, 2 chunks each
    const int sr = tid >> 1;
    const int cb = (tid & 1) * 2;
    auto load_tiles = [&](int s, int kpos) {
        const __half* srcA = A  + (size_t)(mBase + sr) * K + kpos;
        const __half* srcB = Bt + (size_t)(nBase + sr) * K + kpos;
        #pragma unroll
        for (int i = 0; i < 2; i++) {
            int c = cb + i;
            cpa16(asA + (uint32_t)((s * 128 * HSTR + sr * HSTR + c * 8) * 2),
                  srcA + c * 8);
            cpa16(asB + (uint32_t)((s * 128 * HSTR + sr * HSTR + c * 8) * 2),
                  srcB + c * 8);
        }
    };

    float acc[4][4][4] = {};

    const int nIter = (kEnd - kBeg) / 32;
    load_tiles(0, kBeg);
    CP_COMMIT();

    for (int it = 0; it < nIter; ++it) {
        int s = it & 1;
        if (it + 1 < nIter) {
            load_tiles(s ^ 1, kBeg + (it + 1) * 32);
            CP_COMMIT();
            CP_WAIT1();
        } else {
            CP_WAIT0();
        }
        __syncthreads();

        const uint32_t aS = asA + (uint32_t)(s * 128 * HSTR * 2);
        const uint32_t bS = asB + (uint32_t)(s * 128 * HSTR * 2);
        #pragma unroll
        for (int kk = 0; kk < 32; kk += 16) {
            unsigned af[4][4], bf[4][2];
            #pragma unroll
            for (int mt = 0; mt < 4; mt++)
                ldsm_x4(af[mt],
                        aS + (uint32_t)(((a_row + mt * 16) * HSTR + kk + a_kof) * 2));
            #pragma unroll
            for (int nt = 0; nt < 4; nt++)
                ldsm_x2(bf[nt],
                        bS + (uint32_t)(((b_row + nt * 8) * HSTR + kk + b_kof) * 2));
            #pragma unroll
            for (int mt = 0; mt < 4; mt++)
                #pragma unroll
                for (int nt = 0; nt < 4; nt++)
                    mma_f16(acc[mt][nt], af[mt], bf[nt]);
        }
        __syncthreads();
    }

    // ---- epilogue ----
    #pragma unroll
    for (int mt = 0; mt < 4; mt++) {
        int r0 = mBase + wm + mt * 16 + g;
        int r1 = r0 + 8;
        int la0 = 0, la1 = 0, lb0 = 0, lb1 = 0;
        if (MODE == 4) { la0 = lqq[r0] * NNq; la1 = lqq[r1] * NNq; }
        if (MODE == 3) { lb0 = lqq[r0]; lb1 = lqq[r1]; }
        #pragma unroll
        for (int nt = 0; nt < 4; nt++) {
            int c = nBase + wn + nt * 8 + 2 * tig;
            const float* a4 = acc[mt][nt];
            if (MODE == 4) {
                int n0 = c, n1 = c + 1;
                if (n0 < la0) {
                    Cc [(size_t)r0 * ldc + n0] = a4[0];
                    Lab[(size_t)r0 * ldc + n0] = 0.f;
                } else if (n0 >= la0 + NNq) {
                    Cc [(size_t)r0 * ldc + n0 - NNq] = a4[0];
                    Lab[(size_t)r0 * ldc + n0 - NNq] = 0.f;
                }
                if (n1 < la0) {
                    Cc [(size_t)r0 * ldc + n1] = a4[1];
                    Lab[(size_t)r0 * ldc + n1] = 0.f;
                } else if (n1 >= la0 + NNq) {
                    Cc [(size_t)r0 * ldc + n1 - NNq] = a4[1];
                    Lab[(size_t)r0 * ldc + n1 - NNq] = 0.f;
                }
                if (n0 < la1) {
                    Cc [(size_t)r1 * ldc + n0] = a4[2];
                    Lab[(size_t)r1 * ldc + n0] = 0.f;
                } else if (n0 >= la1 + NNq) {
                    Cc [(size_t)r1 * ldc + n0 - NNq] = a4[2];
                    Lab[(size_t)r1 * ldc + n0 - NNq] = 0.f;
                }
                if (n1 < la1) {
                    Cc [(size_t)r1 * ldc + n1] = a4[3];
                    Lab[(size_t)r1 * ldc + n1] = 0.f;
                } else if (n1 >= la1 + NNq) {
                    Cc [(size_t)r1 * ldc + n1 - NNq] = a4[3];
                    Lab[(size_t)r1 * ldc + n1 - NNq] = 0.f;
                }
            } else {
                float bx = 0.f, by = 0.f;
                if (MODE == 0) { bx = bias[c]; by = bias[c + 1]; }
                float2 v0 = { a4[0] + bx, a4[1] + by };
                float2 v1 = { a4[2] + bx, a4[3] + by };
                *(float2*)(Cc + (size_t)r0 * ldc + c) = v0;
                *(float2*)(Cc + (size_t)r1 * ldc + c) = v1;
                if (MODE == 3) {
                    int k0c = lkk[c], k1c = lkk[c + 1];
                    float2 l0 = { (k0c == lb0) ? 1.f : 0.f,
                                  (k1c == lb0) ? 1.f : 0.f };
                    float2 l1 = { (k0c == lb1) ? 1.f : 0.f,
                                  (k1c == lb1) ? 1.f : 0.f };
                    *(float2*)(Lab + (size_t)r0 * ldc + c) = l0;
                    *(float2*)(Lab + (size_t)r1 * ldc + c) = l1;
                }
            }
        }
    }
}

// ---------------- prep: fp32 -> fp16 (8 / thread; q/k via z) ---------------
__global__ void cvt_half_k(const float* __restrict__ in0, const float* __restrict__ in1,
                           __half* __restrict__ o0, __half* __restrict__ o1, int n8)
{
    const float* in = blockIdx.z ? in1 : in0;
    __half* o = blockIdx.z ? o1 : o0;
    int i = blockIdx.x * blockDim.x + threadIdx.x;
    if (i >= n8) return;
    float4 a = ((const float4*)in)[i * 2];
    float4 b = ((const float4*)in)[i * 2 + 1];
    __half h[8];
    h[0] = __float2half_rn(a.x); h[1] = __float2half_rn(a.y);
    h[2] = __float2half_rn(a.z); h[3] = __float2half_rn(a.w);
    h[4] = __float2half_rn(b.x); h[5] = __float2half_rn(b.y);
    h[6] = __float2half_rn(b.z); h[7] = __float2half_rn(b.w);
    ((uint4*)o)[i] = *(const uint4*)h;
}

// ---------------- prep: transpose fp32 [R][C] -> half [C][R] ---------------
__global__ void transpose_half_k(const float* __restrict__ in, __half* __restrict__ out,
                                 int R, int C)
{
    __shared__ float t[32][33];
    int cx = blockIdx.x * 32 + threadIdx.x;
    int ry = blockIdx.y * 32 + threadIdx.y;
    #pragma unroll
    for (int j = 0; j < 32; j += 8)
        t[threadIdx.y + j][threadIdx.x] = in[(size_t)(ry + j) * C + cx];
    __syncthreads();
    int cx2 = blockIdx.y * 32 + threadIdx.x;
    int ry2 = blockIdx.x * 32 + threadIdx.y;
    #pragma unroll
    for (int j = 0; j < 32; j += 8)
        out[(size_t)(ry2 + j) * R + cx2] = __float2half_rn(t[threadIdx.x][threadIdx.y + j]);
}

// ---------------- BN stats -------------------------------------------------
__global__ void bn_stats_k(const float* __restrict__ Hq, const float* __restrict__ Hk,
                           const float* __restrict__ gamma, const float* __restrict__ beta,
                           float* __restrict__ scq, float* __restrict__ shq,
                           float* __restrict__ sck, float* __restrict__ shk)
{
    const float* H = blockIdx.z ? Hk : Hq;
    float* scale = blockIdx.z ? sck : scq;
    float* shift = blockIdx.z ? shk : shq;
    int f = blockIdx.x * 32 + threadIdx.x;
    float s = 0.f, ss = 0.f;
    for (int r = threadIdx.y; r < Bsz; r += 32) {
        float v = H[(size_t)r * DF + f];
        s += v; ss += v * v;
    }
    __shared__ float sh_s[32][33], sh_ss[32][33];
    sh_s[threadIdx.y][threadIdx.x]  = s;
    sh_ss[threadIdx.y][threadIdx.x] = ss;
    __syncthreads();
    if (threadIdx.y == 0) {
        #pragma unroll
        for (int y = 1; y < 32; y++) {
            s += sh_s[y][threadIdx.x]; ss += sh_ss[y][threadIdx.x];
        }
        float mu  = s * (1.f / Bsz);
        float var = ss * (1.f / Bsz) - mu * mu;
        float rst = rsqrtf(var + 1e-5f);
        float scv = rst * gamma[f];
        scale[f] = scv;
        shift[f] = beta[f] - mu * scv;
    }
}

// ---------------- BN apply + relu -> half ----------------------------------
__global__ void bnrelu_half_k(const float* __restrict__ Hq, const float* __restrict__ Hk,
                              __half* __restrict__ Rq, __half* __restrict__ Rk)
{
    const float* H = blockIdx.z ? Hk : Hq;
    __half* R = blockIdx.z ? Rk : Rq;
    const float* sc = blockIdx.z ? g_sck : g_scq;
    const float* sh = blockIdx.z ? g_shk : g_shq;
    int i = blockIdx.x * blockDim.x + threadIdx.x;   // 8-float group
    int f = (i * 8) & (DF - 1);
    float4 a = ((const float4*)H)[i * 2];
    float4 b = ((const float4*)H)[i * 2 + 1];
    float4 sa = *(const float4*)(sc + f);
    float4 sb = *(const float4*)(sc + f + 4);
    float4 ha = *(const float4*)(sh + f);
    float4 hb = *(const float4*)(sh + f + 4);
    __half h[8];
    h[0] = __float2half_rn(fmaxf(fmaf(a.x, sa.x, ha.x), 0.f));
    h[1] = __float2half_rn(fmaxf(fmaf(a.y, sa.y, ha.y), 0.f));
    h[2] = __float2half_rn(fmaxf(fmaf(a.z, sa.z, ha.z), 0.f));
    h[3] = __float2half_rn(fmaxf(fmaf(a.w, sa.w, ha.w), 0.f));
    h[4] = __float2half_rn(fmaxf(fmaf(b.x, sb.x, hb.x), 0.f));
    h[5] = __float2half_rn(fmaxf(fmaf(b.y, sb.y, hb.y), 0.f));
    h[6] = __float2half_rn(fmaxf(fmaf(b.z, sb.z, hb.z), 0.f));
    h[7] = __float2half_rn(fmaxf(fmaf(b.w, sb.w, hb.w), 0.f));
    ((uint4*)R)[i] = *(const uint4*)h;
}

// ---------------- split-K reduce + bias + l2norm ---------------------------
__global__ void reduce_l2_k(const float* __restrict__ b2)
{
    int qk = blockIdx.y, b = blockIdx.x, d = threadIdx.x;  // d: 0..127
    const float* part = g_fpart + (size_t)qk * SPLITK * Bsz * DIM;
    float v = b2[d];
    #pragma unroll
    for (int s = 0; s < SPLITK; s++)
        v += part[(size_t)s * Bsz * DIM + (size_t)b * DIM + d];
    float ss = v * v;
    #pragma unroll
    for (int o = 16; o; o >>= 1) ss += __shfl_xor_sync(0xffffffffu, ss, o);
    __shared__ float ws[4];
    if ((d & 31) == 0) ws[d >> 5] = ss;
    __syncthreads();
    ss = ws[0] + ws[1] + ws[2] + ws[3];
    float inv = 1.f / fmaxf(sqrtf(ss), 1e-12f);
    float vn = v * inv;
    if (qk) {
        g_featk[(size_t)b * DIM + d] = vn;
        g_featkH[(size_t)b * DIM + d] = __float2half_rn(vn);
    } else {
        g_featq[(size_t)b * DIM + d] = vn;
        g_featqH[(size_t)b * DIM + d] = __float2half_rn(vn);
    }
}

// ---------------- pos_list (+ ones into labels) ----------------------------
__global__ void pos_k(const int* __restrict__ lq, const float* __restrict__ posq,
                      float* __restrict__ out)
{
    int b = blockIdx.x, tid = threadIdx.x;
    __shared__ float fr[DIM];
    if (tid < DIM) fr[tid] = g_featq[(size_t)b * DIM + tid];
    __syncthreads();
    int w = tid >> 5, lane = tid & 31;
    int col = lq[b] * PP + w;
    float s = 0.f;
    for (int d = lane; d < DIM; d += 32)
        s += fr[d] * posq[(size_t)d * PC + col];
    #pragma unroll
    for (int o = 16; o; o >>= 1) s += __shfl_down_sync(0xffffffffu, s, o);
    if (lane == 0) {
        out[OFF_SIM + (size_t)b * SIMW + Bsz + w] = s;
        out[OFF_LAB + (size_t)b * SIMW + Bsz + w] = 1.f;
    }
}

// ---------------- occurrence rank + count (warp-per-row) -------------------
__global__ void rank_k(const int* __restrict__ lk)
{
    __shared__ int sl[Bsz];
    int t = threadIdx.y * 32 + threadIdx.x;
    for (int i = t; i < Bsz; i += 1024) sl[i] = lk[i];
    __syncthreads();
    int b = blockIdx.x * 32 + threadIdx.y;
    int lab = sl[b];
    int r = 0, c = 0;
    for (int j = threadIdx.x; j < Bsz; j += 32) {
        int e = (sl[j] == lab);
        c += e;
        r += e & (j < b);
    }
    #pragma unroll
    for (int o = 16; o; o >>= 1) {
        c += __shfl_down_sync(0xffffffffu, c, o);
        r += __shfl_down_sync(0xffffffffu, r, o);
    }
    if (threadIdx.x == 0) { g_rank[b] = r; g_cntb[b] = c; }
}

// ---------------- ptr outputs (warp-per-class) -----------------------------
__global__ void ptr_k(const int* __restrict__ lk, const int* __restrict__ nptr,
                      const int* __restrict__ pptr, float* __restrict__ out)
{
    __shared__ int sl[Bsz];
    for (int i = threadIdx.x; i < Bsz; i += 256) sl[i] = lk[i];
    __syncthreads();
    int w = threadIdx.x >> 5, lane = threadIdx.x & 31;
    int c = blockIdx.x * 8 + w;
    int cnt = 0;
    for (int j = lane; j < Bsz; j += 32) cnt += (sl[j] == c);
    #pragma unroll
    for (int o = 16; o; o >>= 1) cnt += __shfl_down_sync(0xffffffffu, cnt, o);
    if (lane == 0) {
        out[OFF_NPTR + c] = (float)((nptr[c] + cnt) % NNq);
        out[OFF_PPTR + c] = (float)((pptr[c] + cnt) % PP);
    }
}

// ---------------- queue overwrite ------------------------------------------
__global__ void queue_update_k(const int* __restrict__ lk, const int* __restrict__ nptr,
                               const int* __restrict__ pptr, float* __restrict__ out)
{
    int b = blockIdx.x;
    int d = threadIdx.x;   // 128
    int lab = lk[b];
    int r = g_rank[b];
    int c = g_cntb[b];
    float v = g_featk[(size_t)b * DIM + d];
    if (r >= c - NNq) {
        int slot = (nptr[lab] + r) % NNq;
        out[OFF_NQ2 + (size_t)d * NC + lab * NNq + slot] = v;
    }
    if (r >= c - PP) {
        int slot = (pptr[lab] + r) % PP;
        out[OFF_PQ2 + (size_t)d * PC + lab * PP + slot] = v;
    }
}

// ---------------- host launcher --------------------------------------------
static void* symp(const void* sym) {
    void* p = nullptr;
    cudaGetSymbolAddress(&p, sym);
    return p;
}

extern "C" void kernel_launch(void* const* d_in, const int* in_sizes, int n_in,
                              void* d_out, int out_size)
{
    (void)in_sizes; (void)n_in; (void)out_size;
    const float* midq  = (const float*)d_in[0];
    const float* midk  = (const float*)d_in[1];
    const int*   lq    = (const int*)d_in[2];
    const int*   lk    = (const int*)d_in[3];
    const float* W1    = (const float*)d_in[4];
    const float* b1    = (const float*)d_in[5];
    const float* gamma = (const float*)d_in[6];
    const float* beta  = (const float*)d_in[7];
    const float* W2    = (const float*)d_in[8];
    const float* b2    = (const float*)d_in[9];
    const float* Wlin  = (const float*)d_in[10];
    const float* blin  = (const float*)d_in[11];
    const float* negq  = (const float*)d_in[12];
    const float* posq  = (const float*)d_in[13];
    const int*   nptr  = (const int*)d_in[14];
    const int*   pptr  = (const int*)d_in[15];
    float* out = (float*)d_out;

    float*  Hq     = (float*)symp(g_Hq);
    float*  Hk     = (float*)symp(g_Hk);
    __half* midqH  = (__half*)symp(g_midqH);
    __half* midkH  = (__half*)symp(g_midkH);
    __half* HqH    = (__half*)symp(g_HqH);
    __half* HkH    = (__half*)symp(g_HkH);
    __half* W1T    = (__half*)symp(g_W1T);
    __half* WlinT  = (__half*)symp(g_WlinT);
    __half* W2T    = (__half*)symp(g_W2T);
    __half* negT   = (__half*)symp(g_negT);
    float*  scq = (float*)symp(g_scq); float* shq = (float*)symp(g_shq);
    float*  sck = (float*)symp(g_sck); float* shk = (float*)symp(g_shk);
    __half* fqH = (__half*)symp(g_featqH);
    __half* fkH = (__half*)symp(g_featkH);
    float*  fpart = (float*)symp(g_fpart);

    // queues copied to output (queue_update overwrites survivors)
    cudaMemcpyAsync(out + OFF_NQ2, negq, sizeof(float) * (size_t)DIM * NC,
                    cudaMemcpyDeviceToDevice);
    cudaMemcpyAsync(out + OFF_PQ2, posq, sizeof(float) * (size_t)DIM * PC,
                    cudaMemcpyDeviceToDevice);

    // ---- prep: convert activations; transpose+convert weights ----
    cvt_half_k<<<dim3(Bsz * DF / 8 / 256, 1, 2), 256>>>(
        midq, midk, midqH, midkH, Bsz * DF / 8);
    transpose_half_k<<<dim3(CC / 32, DF / 32), dim3(32, 8)>>>(Wlin, WlinT, DF, CC);
    transpose_half_k<<<dim3(DF / 32, DF / 32), dim3(32, 8)>>>(W1, W1T, DF, DF);
    transpose_half_k<<<dim3(DIM / 32, DF / 32), dim3(32, 8)>>>(W2, W2T, DF, DIM);
    transpose_half_k<<<dim3(NC / 32, DIM / 32), dim3(32, 8)>>>(negq, negT, DIM, NC);

    // ---- logits: mid @ Wlin + blin ----
    hgemm_k<0><<<dim3(CC / 128, Bsz / 128, 2), 256>>>(
        midqH, midkH, WlinT, blin, out + OFF_LQ, out + OFF_LK,
        DF, CC, nullptr, nullptr, nullptr);

    // ---- H = mid @ W1 + b1 ----
    hgemm_k<0><<<dim3(DF / 128, Bsz / 128, 2), 256>>>(
        midqH, midkH, W1T, b1, Hq, Hk, DF, DF, nullptr, nullptr, nullptr);

    // ---- BN stats + apply(relu) -> half ----
    bn_stats_k<<<dim3(DF / 32, 1, 2), dim3(32, 32)>>>(
        Hq, Hk, gamma, beta, scq, shq, sck, shk);
    bnrelu_half_k<<<dim3(Bsz * DF / 8 / 256, 1, 2), 256>>>(Hq, Hk, HqH, HkH);

    // ---- feat partials = relu(BN(H)) @ W2 (split-K 16, q/k via z) ----
    hgemm_k<2><<<dim3(1, Bsz / 128, 2 * SPLITK), 256>>>(
        HqH, HkH, W2T, nullptr, fpart, nullptr, DF, DIM,
        nullptr, nullptr, nullptr);

    // ---- reduce + bias + l2norm (fp32 + half feats) ----
    reduce_l2_k<<<dim3(Bsz, 2), DIM>>>(b2);

    // ---- sim_batch = feat_q @ feat_k^T (+ labels fused); featkH is [N][K] ----
    hgemm_k<3><<<dim3(Bsz / 128, Bsz / 128, 1), 256>>>(
        fqH, nullptr, fkH, nullptr, out + OFF_SIM, nullptr, DIM, SIMW,
        lq, lk, out + OFF_LAB);

    // ---- pos_list (+ ones) ----
    pos_k<<<Bsz, 256>>>(lq, posq, out);

    // ---- neg gathered (+ zeros into labels) ----
    hgemm_k<4><<<dim3(NC / 128, Bsz / 128, 1), 256>>>(
        fqH, nullptr, negT, nullptr, out + OFF_SIM + Bsz + PP, nullptr,
        DIM, SIMW, lq, nullptr, out + OFF_LAB + Bsz + PP);

    // ---- queue update ----
    rank_k<<<32, dim3(32, 32)>>>(lk);
    ptr_k<<<CC / 8, 256>>>(lk, nptr, pptr, out);
    queue_update_k<<<Bsz, DIM>>>(lk, nptr, pptr, out);
}